// round 6
// baseline (speedup 1.0000x reference)
#include <cuda_runtime.h>

#define BB 1024
#define T_HIST 50
#define ENC_IN 96
#define ENC_H 128
#define G4 (4*ENC_H)          // 512
#define CDE_H 64
#define CHN 33
#define NZ 10000
#define MLP_H 128
#define W2_ROWS (CHN*CDE_H)   // 2112
#define N_STEPS 16

// ----------------------------------------------------------------------------
// Scratch (static device globals — no allocation)
// ----------------------------------------------------------------------------
__device__ float g_xW[BB*T_HIST*G4];      // input-to-hidden precompute (both layers, reused)
__device__ float g_seq0[BB*T_HIST*ENC_H]; // layer-0 hidden sequence
__device__ float g_h1[2][BB*ENC_H];       // layer-1 h ping-pong
__device__ float g_z[BB*CDE_H];           // CDE state
__device__ float g_k[6][BB*CDE_H];        // RK45 stage derivatives
__device__ float g_a[BB*MLP_H];           // relu(zn@W1^T + b1)
__device__ float g_f[BB*W2_ROWS];         // tanh(a@W2^T + b2)

// global grid barrier state (persistent LSTM)
__device__ unsigned g_barGen;
__device__ unsigned g_barCnt;

// ----------------------------------------------------------------------------
// Packed f32x2 helpers (2 fp32 FMAs per issue slot — ptxas never emits this)
// ----------------------------------------------------------------------------
__device__ __forceinline__ void ffma2(unsigned long long &d,
                                      unsigned long long a, unsigned long long b) {
    asm("fma.rn.f32x2 %0, %1, %2, %0;" : "+l"(d) : "l"(a), "l"(b));
}
__device__ __forceinline__ unsigned long long dup2(float x) {
    unsigned long long r; asm("mov.b64 %0, {%1, %1};" : "=l"(r) : "f"(x)); return r;
}
__device__ __forceinline__ float2 upk2(unsigned long long v) {
    float2 r; asm("mov.b64 {%0, %1}, %2;" : "=f"(r.x), "=f"(r.y) : "l"(v)); return r;
}
union F4U { float4 f; unsigned long long u[2]; };

// ----------------------------------------------------------------------------
// Grid-wide barrier for co-resident persistent kernels.
// ----------------------------------------------------------------------------
__device__ __forceinline__ void grid_bar(unsigned &gen, int ncta) {
    __syncthreads();
    if (threadIdx.x == 0) {
        __threadfence();
        unsigned a = atomicAdd(&g_barCnt, 1u);
        if (a == (unsigned)(ncta - 1)) {
            g_barCnt = 0;
            __threadfence();
            atomicAdd(&g_barGen, 1u);
        } else {
            while (atomicAdd(&g_barGen, 0u) <= gen) { __nanosleep(32); }
        }
    }
    gen++;
    __syncthreads();
}

// ----------------------------------------------------------------------------
// Generic C = act(A @ B^T + bias). A:[M,K], B:[N,K], row-major, K%16==0, M%64==0.
// 64x64 tile, 256 threads, 4x4 microtile done as 2 row-pairs x 4 cols in f32x2.
// ACT: 0 none, 1 tanh, 2 relu
// ----------------------------------------------------------------------------
template<int ACT>
__global__ void __launch_bounds__(256)
gemm_tn(const float* __restrict__ A, const float* __restrict__ Bm,
        const float* __restrict__ bias, float* __restrict__ C,
        int M, int N, int K)
{
    __shared__ __align__(16) float As[16][64];
    __shared__ __align__(16) float Bs[16][64];
    const int m0 = blockIdx.x * 64;
    const int n0 = blockIdx.y * 64;
    const int tid = threadIdx.x;
    const int tr = tid >> 4;   // 0..15 -> rows tr*4..tr*4+3
    const int tc = tid & 15;   // 0..15 -> cols tc*4..tc*4+3

    unsigned long long acc[2][4] = {};   // row-pairs (tr*4+2p, +2p+1) x 4 cols

    const int ml = tid >> 2;          // 0..63
    const int kq = (tid & 3) * 4;     // 0,4,8,12

    for (int k0 = 0; k0 < K; k0 += 16) {
        {
            float4 v = *(const float4*)(A + (size_t)(m0 + ml) * K + k0 + kq);
            As[kq+0][ml] = v.x; As[kq+1][ml] = v.y; As[kq+2][ml] = v.z; As[kq+3][ml] = v.w;
            float4 w = make_float4(0.f, 0.f, 0.f, 0.f);
            if (n0 + ml < N)
                w = *(const float4*)(Bm + (size_t)(n0 + ml) * K + k0 + kq);
            Bs[kq+0][ml] = w.x; Bs[kq+1][ml] = w.y; Bs[kq+2][ml] = w.z; Bs[kq+3][ml] = w.w;
        }
        __syncthreads();
#pragma unroll
        for (int kk = 0; kk < 16; kk++) {
            F4U a; a.f = *(const float4*)&As[kk][tr*4];
            F4U b; b.f = *(const float4*)&Bs[kk][tc*4];
            unsigned long long bd[4] = {dup2(b.f.x), dup2(b.f.y), dup2(b.f.z), dup2(b.f.w)};
#pragma unroll
            for (int p = 0; p < 2; p++)
#pragma unroll
                for (int j = 0; j < 4; j++) ffma2(acc[p][j], a.u[p], bd[j]);
        }
        __syncthreads();
    }

#pragma unroll
    for (int j = 0; j < 4; j++) {
        int n = n0 + tc*4 + j;
        if (n >= N) continue;
        float bb = bias ? bias[n] : 0.f;
#pragma unroll
        for (int p = 0; p < 2; p++) {
            float2 v2 = upk2(acc[p][j]);
            float vv[2] = {v2.x, v2.y};
#pragma unroll
            for (int d = 0; d < 2; d++) {
                float v = vv[d] + bb;
                if (ACT == 1) v = tanhf(v);
                else if (ACT == 2) v = fmaxf(v, 0.f);
                C[(size_t)(m0 + tr*4 + 2*p + d) * N + n] = v;
            }
        }
    }
}

// ----------------------------------------------------------------------------
// Persistent LSTM layer: 128 CTAs (32 batch x 32 h tile each), all 50 timesteps
// in one launch with grid barriers. Whh slice cached in dynamic smem once;
// cell state in registers; cross-CTA h via __ldcg after barrier.
// mode 0: h_buf laid out [b][t][H] (seq, stride h_sb=T*H, t-offset t*H)
// mode 1: ping-pong      [t&1][b][H] (h_sb=H, t-offset (t&1)*B*H)
// ----------------------------------------------------------------------------
__global__ void __launch_bounds__(256)
lstm_persist(const float* __restrict__ xw,      // [B][T][G4]
             const float* __restrict__ Whh,     // [G4][ENC_H]
             const float* __restrict__ bih, const float* __restrict__ bhh,
             float* __restrict__ h_buf, int h_sb, int mode, int nsteps)
{
    extern __shared__ __align__(16) float Wsm[];          // [128 k][128 c] = 64KB
    __shared__ __align__(16) float As[ENC_H][36];          // [k][m], padded
    __shared__ float Gs[32][132];
    __shared__ float bsum[128];

    const int b0 = (blockIdx.x & 31) * 32;
    const int h0 = (blockIdx.x >> 5) * 32;
    const int tid = threadIdx.x;
    const int tr = tid >> 5;   // 0..7 -> rows tr*4..+3
    const int tc = tid & 31;   // cols tc*4..+3 of 128 gate-cols

    // one-time weight load into smem: Wsm[k*128 + c] = Whh[jg(c)][k]
    for (int e = tid; e < 128*32; e += 256) {
        int c = e & 127, kq = (e >> 7) * 4;
        int jg = (c >> 5) * ENC_H + h0 + (c & 31);
        float4 v = *(const float4*)(Whh + (size_t)jg * ENC_H + kq);
        Wsm[(kq+0)*128 + c] = v.x; Wsm[(kq+1)*128 + c] = v.y;
        Wsm[(kq+2)*128 + c] = v.z; Wsm[(kq+3)*128 + c] = v.w;
    }
    if (tid < 128) {
        int jg = (tid >> 5) * ENC_H + h0 + (tid & 31);
        bsum[tid] = bih[jg] + bhh[jg];
    }
    unsigned gen = atomicAdd(&g_barGen, 0u);
    float creg[4] = {0.f, 0.f, 0.f, 0.f};
    __syncthreads();

    for (int t = 0; t < nsteps; t++) {
        unsigned long long acc[2][4] = {};
        if (t > 0) {
            const float* hp = h_buf + (mode ? (size_t)((t-1) & 1) * BB * ENC_H
                                            : (size_t)(t-1) * ENC_H);
            // stage 32 rows x 128 k of h_prev (L2 via __ldcg)
#pragma unroll
            for (int q = 0; q < 4; q++) {
                int e = tid + q * 256;       // 0..1023
                int m = e & 31, kq = (e >> 5) * 4;
                float4 v = __ldcg((const float4*)(hp + (size_t)(b0 + m) * h_sb + kq));
                As[kq+0][m] = v.x; As[kq+1][m] = v.y; As[kq+2][m] = v.z; As[kq+3][m] = v.w;
            }
            __syncthreads();
#pragma unroll 4
            for (int kk = 0; kk < ENC_H; kk++) {
                F4U a; a.f = *(const float4*)&As[kk][tr*4];
                F4U b; b.f = *(const float4*)&Wsm[kk*128 + tc*4];
                unsigned long long bd[4] = {dup2(b.f.x), dup2(b.f.y), dup2(b.f.z), dup2(b.f.w)};
#pragma unroll
                for (int p = 0; p < 2; p++)
#pragma unroll
                    for (int j = 0; j < 4; j++) ffma2(acc[p][j], a.u[p], bd[j]);
            }
        }

        // epilogue: gate pre-activations into Gs
#pragma unroll
        for (int j = 0; j < 4; j++) {
            int c = tc*4 + j;
            int jg = (c >> 5) * ENC_H + h0 + (c & 31);
            float bb = bsum[c];
#pragma unroll
            for (int p = 0; p < 2; p++) {
                float2 v2 = upk2(acc[p][j]);
                float vv[2] = {v2.x, v2.y};
#pragma unroll
                for (int d = 0; d < 2; d++) {
                    int r = tr*4 + 2*p + d;
                    Gs[r][c] = vv[d] + xw[(size_t)(b0 + r) * (T_HIST*G4) + (size_t)t * G4 + jg] + bb;
                }
            }
        }
        __syncthreads();

        // gates + c/h update (c lives in registers: fixed (r,hh) per thread)
        float* ho = h_buf + (mode ? (size_t)(t & 1) * BB * ENC_H : (size_t)t * ENC_H);
#pragma unroll
        for (int q = 0; q < 4; q++) {
            int e = tid + q * 256;
            int r = e >> 5, hh = e & 31;
            float gi = Gs[r][hh];
            float gf = Gs[r][32 + hh];
            float gg = Gs[r][64 + hh];
            float go = Gs[r][96 + hh];
            float si = 1.f / (1.f + expf(-gi));
            float sf = 1.f / (1.f + expf(-gf));
            float so = 1.f / (1.f + expf(-go));
            float tg = tanhf(gg);
            float cn = sf * creg[q] + si * tg;
            creg[q] = cn;
            float hn = so * tanhf(cn);
            ho[(size_t)(b0 + r) * h_sb + h0 + hh] = hn;
        }
        if (t + 1 < nsteps) grid_bar(gen, (int)gridDim.x);
    }
}

// ----------------------------------------------------------------------------
// Fused CDE kernel: [optional] contract(stage sidx) -> k / z-update, then
// [optional] prep(next stage): stage combine + LayerNorm + relu(zn@W1^T+b1).
// Batch-row-local: CTA b owns rows b0..b0+31. grid = B/32, 256 threads.
// ----------------------------------------------------------------------------
__global__ void __launch_bounds__(256)
cde_fused(const float* __restrict__ coeffs,
          const float* __restrict__ gamma, const float* __restrict__ beta,
          const float* __restrict__ W1, const float* __restrict__ b1,
          int do_contract, int sidx, int idx, float u, int is_last,
          float c1, float c3, float c4, float c5, float c6,
          int do_prep, float a0, float a1, float a2, float a3, float a4, int nk)
{
    __shared__ __align__(16) float pool[8192];       // zs[32*65] + dX[32*33]; later W1s[64*128]
    __shared__ __align__(16) float znT[64][36];
    __shared__ float mu[32], rstd[32];
    float* zs  = pool;           // [r*65 + k]
    float* dXs = pool + 2080;    // [r*33 + ch]
    const int b0 = blockIdx.x * 32;
    const int tid = threadIdx.x;

    if (do_contract) {
        for (int e = tid; e < 32 * CHN; e += 256) {
            int r = e / CHN, ch = e - r * CHN;
            size_t base = ((size_t)(b0 + r) * 4 + idx) * (4 * CHN);
            float A1 = coeffs[base + CHN + ch];
            float A2 = coeffs[base + 2 * CHN + ch];
            float A3 = coeffs[base + 3 * CHN + ch];
            dXs[r * CHN + ch] = A1 + 2.f * A2 * u + 3.f * A3 * u * u;
        }
        __syncthreads();
        const float av[5] = {a0, a1, a2, a3, a4};
#pragma unroll
        for (int q = 0; q < 8; q++) {
            int e = tid + q * 256;
            int r = e >> 6, h = e & 63;
            const float* fr = g_f + (size_t)(b0 + r) * W2_ROWS + h * CHN;
            const float* dx = &dXs[r * CHN];
            float acc = 0.f;
#pragma unroll
            for (int ch = 0; ch < CHN; ch++) acc += fr[ch] * dx[ch];
            size_t gi = (size_t)(b0 + r) * CDE_H + h;
            if (is_last) {
                float z = g_z[gi] + c1 * g_k[0][gi] + c3 * g_k[2][gi]
                        + c4 * g_k[3][gi] + c5 * g_k[4][gi] + c6 * acc;
                g_z[gi] = z;
                zs[r * 65 + h] = z;
            } else {
                g_k[sidx][gi] = acc;
                float v = g_z[gi];
                for (int j = 0; j < nk; j++)
                    v += av[j] * ((j == sidx) ? acc : g_k[j][gi]);
                zs[r * 65 + h] = v;
            }
        }
    } else {
#pragma unroll
        for (int q = 0; q < 8; q++) {
            int e = tid + q * 256;
            int r = e >> 6, h = e & 63;
            zs[r * 65 + h] = g_z[(size_t)(b0 + r) * CDE_H + h];
        }
    }
    if (!do_prep) return;
    __syncthreads();

    // LayerNorm stats: 8 lanes per row, two-pass, butterfly reduce
    {
        int row = tid >> 3, lane = tid & 7;
        float s = 0.f;
        for (int k = lane; k < 64; k += 8) s += zs[row * 65 + k];
#pragma unroll
        for (int d = 1; d < 8; d <<= 1) s += __shfl_xor_sync(0xffffffffu, s, d, 8);
        float m = s * (1.f / 64.f);
        float q2 = 0.f;
        for (int k = lane; k < 64; k += 8) { float dd = zs[row * 65 + k] - m; q2 += dd * dd; }
#pragma unroll
        for (int d = 1; d < 8; d <<= 1) q2 += __shfl_xor_sync(0xffffffffu, q2, d, 8);
        if (lane == 0) { mu[row] = m; rstd[row] = rsqrtf(q2 * (1.f / 64.f) + 1e-5f); }
    }
    __syncthreads();
#pragma unroll
    for (int q = 0; q < 8; q++) {
        int e = tid + q * 256;
        int k = e >> 5, r = e & 31;
        znT[k][r] = (zs[r * 65 + k] - mu[r]) * rstd[r] * gamma[k] + beta[k];
    }
    __syncthreads();

    // W1 transposed into pool (overwrites zs/dXs)
    float* W1s = pool;
#pragma unroll
    for (int q = 0; q < 32; q++) {
        int e = tid + q * 256;               // 0..8191
        int j = e >> 6, k = e & 63;
        W1s[k * 128 + j] = W1[e];
    }
    __syncthreads();

    const int tr = tid >> 5;   // rows tr*4
    const int tc = tid & 31;   // cols tc*4 of 128
    unsigned long long acc[2][4] = {};
#pragma unroll 4
    for (int k = 0; k < 64; k++) {
        F4U a; a.f = *(const float4*)&znT[k][tr*4];
        F4U b; b.f = *(const float4*)&W1s[k * 128 + tc*4];
        unsigned long long bd[4] = {dup2(b.f.x), dup2(b.f.y), dup2(b.f.z), dup2(b.f.w)};
#pragma unroll
        for (int p = 0; p < 2; p++)
#pragma unroll
            for (int j = 0; j < 4; j++) ffma2(acc[p][j], a.u[p], bd[j]);
    }
#pragma unroll
    for (int j = 0; j < 4; j++) {
        int col = tc*4 + j;
        float bb = b1[col];
#pragma unroll
        for (int p = 0; p < 2; p++) {
            float2 v2 = upk2(acc[p][j]);
            float vv[2] = {v2.x, v2.y};
#pragma unroll
            for (int d = 0; d < 2; d++) {
                g_a[(size_t)(b0 + tr*4 + 2*p + d) * MLP_H + col] = fmaxf(vv[d] + bb, 0.f);
            }
        }
    }
}

// ----------------------------------------------------------------------------
// Host orchestration
// ----------------------------------------------------------------------------
extern "C" void kernel_launch(void* const* d_in, const int* in_sizes, int n_in,
                              void* d_out, int out_size)
{
    const float* hist   = (const float*)d_in[0];
    const float* coeffs = (const float*)d_in[1];
    // d_in[2] = cde_times = [0,1] (deterministic; baked in)
    const float* W_ih0 = (const float*)d_in[3];
    const float* W_hh0 = (const float*)d_in[4];
    const float* b_ih0 = (const float*)d_in[5];
    const float* b_hh0 = (const float*)d_in[6];
    const float* W_ih1 = (const float*)d_in[7];
    const float* W_hh1 = (const float*)d_in[8];
    const float* b_ih1 = (const float*)d_in[9];
    const float* b_hh1 = (const float*)d_in[10];
    const float* W_map = (const float*)d_in[11];
    const float* b_map = (const float*)d_in[12];
    const float* gamma = (const float*)d_in[13];
    const float* beta  = (const float*)d_in[14];
    const float* W1    = (const float*)d_in[15];
    const float* b1    = (const float*)d_in[16];
    const float* W2    = (const float*)d_in[17];
    const float* b2    = (const float*)d_in[18];
    const float* W_pred = (const float*)d_in[19];
    const float* b_pred = (const float*)d_in[20];
    float* out = (float*)d_out;

    float *p_xW, *p_seq0, *p_h1, *p_z, *p_a, *p_f;
    cudaGetSymbolAddress((void**)&p_xW,   g_xW);
    cudaGetSymbolAddress((void**)&p_seq0, g_seq0);
    cudaGetSymbolAddress((void**)&p_h1,   g_h1);
    cudaGetSymbolAddress((void**)&p_z,    g_z);
    cudaGetSymbolAddress((void**)&p_a,    g_a);
    cudaGetSymbolAddress((void**)&p_f,    g_f);

    const int WSM_BYTES = 128 * 128 * 4;   // 64KB dynamic smem for Whh slice
    cudaFuncSetAttribute(lstm_persist, cudaFuncAttributeMaxDynamicSharedMemorySize, WSM_BYTES);

    // ---------------- LSTM layer 0 ----------------
    gemm_tn<0><<<dim3(BB*T_HIST/64, G4/64), 256>>>(hist, W_ih0, nullptr, p_xW,
                                                   BB*T_HIST, G4, ENC_IN);
    lstm_persist<<<128, 256, WSM_BYTES>>>(p_xW, W_hh0, b_ih0, b_hh0,
                                          p_seq0, T_HIST*ENC_H, 0, T_HIST);

    // ---------------- LSTM layer 1 ----------------
    gemm_tn<0><<<dim3(BB*T_HIST/64, G4/64), 256>>>(p_seq0, W_ih1, nullptr, p_xW,
                                                   BB*T_HIST, G4, ENC_H);
    lstm_persist<<<128, 256, WSM_BYTES>>>(p_xW, W_hh1, b_ih1, b_hh1,
                                          p_h1, ENC_H, 1, T_HIST);
    const float* context = p_h1 + (size_t)((T_HIST - 1) & 1) * BB * ENC_H;

    // ---------------- map to z0 ----------------
    gemm_tn<1><<<dim3(BB/64, 1), 256>>>(context, W_map, b_map, p_z, BB, CDE_H, ENC_H);

    // ---------------- Neural CDE, RK45 (Dormand-Prince) ----------------
    const double dt = 1.0 / N_STEPS;
    const double ACF[6][5] = {
        {0, 0, 0, 0, 0},
        {1.0/5, 0, 0, 0, 0},
        {3.0/40, 9.0/40, 0, 0, 0},
        {44.0/45, -56.0/15, 32.0/9, 0, 0},
        {19372.0/6561, -25360.0/2187, 64448.0/6561, -212.0/729, 0},
        {9017.0/3168, -355.0/33, 46732.0/5247, 49.0/176, -5103.0/18656}
    };
    const double COFF[6] = {0.0, 1.0/5, 3.0/10, 4.0/5, 8.0/9, 1.0};
    const double BU[5] = {35.0/384, 500.0/1113, 125.0/192, -2187.0/6784, 11.0/84};

    // initial prep (step 0, stage 0): no contract, nk=0
    cde_fused<<<BB/32, 256>>>(coeffs, gamma, beta, W1, b1,
        0, 0, 0, 0.f, 0, 0.f, 0.f, 0.f, 0.f, 0.f,
        1, 0.f, 0.f, 0.f, 0.f, 0.f, 0);

    for (int i = 0; i < N_STEPS; i++) {
        for (int s = 0; s < 6; s++) {
            gemm_tn<1><<<dim3(BB/64, W2_ROWS/64), 256>>>(p_a, W2, b2, p_f,
                                                         BB, W2_ROWS, MLP_H);
            float ts = (float)((i + COFF[s]) * dt);
            int idx = (int)floorf(ts / 0.25f);
            if (idx < 0) idx = 0;
            if (idx > 3) idx = 3;
            float u = ts - (float)idx * 0.25f;

            int last = (s == 5);
            int do_prep = !(i == N_STEPS - 1 && s == 5);
            int nk = last ? 0 : (s + 1);
            const double* ar = last ? ACF[0] : ACF[s + 1];

            cde_fused<<<BB/32, 256>>>(coeffs, gamma, beta, W1, b1,
                1, s, idx, u, last,
                (float)(dt*BU[0]), (float)(dt*BU[1]), (float)(dt*BU[2]),
                (float)(dt*BU[3]), (float)(dt*BU[4]),
                do_prep,
                (float)(dt*ar[0]), (float)(dt*ar[1]), (float)(dt*ar[2]),
                (float)(dt*ar[3]), (float)(dt*ar[4]), nk);
        }
    }

    // ---------------- final projection ----------------
    gemm_tn<0><<<dim3(BB/64, (NZ + 63)/64), 256>>>(p_z, W_pred, b_pred, out,
                                                   BB, NZ, CDE_H);
}

// round 7
// speedup vs baseline: 1.5740x; 1.5740x over previous
#include <cuda_runtime.h>

#define BB 1024
#define T_HIST 50
#define ENC_IN 96
#define ENC_H 128
#define G4 (4*ENC_H)          // 512
#define CDE_H 64
#define CHN 33
#define NZ 10000
#define MLP_H 128
#define W2_ROWS (CHN*CDE_H)   // 2112
#define N_STEPS 16

// ----------------------------------------------------------------------------
// Scratch (static device globals — no allocation)
// ----------------------------------------------------------------------------
__device__ float g_xW[BB*T_HIST*G4];      // input-to-hidden precompute (both layers, reused)
__device__ float g_seq0[BB*T_HIST*ENC_H]; // layer-0 hidden sequence
__device__ float g_h1[2][BB*ENC_H];       // layer-1 h ping-pong
__device__ float g_z[BB*CDE_H];           // CDE state
__device__ float g_k[6][BB*CDE_H];        // RK45 stage derivatives
__device__ float g_a[BB*MLP_H];           // relu(zn@W1^T + b1)
__device__ float g_f[BB*W2_ROWS];         // tanh(a@W2^T + b2)

// global grid barrier state (persistent LSTM)
__device__ unsigned g_barGen;
__device__ unsigned g_barCnt;

// ----------------------------------------------------------------------------
// Grid-wide barrier for co-resident persistent kernels.
// Arrival via L2 atomic; polling via plain L2 load (__ldcg) — no atomic-ALU
// serialization across 128 polling CTAs.
// ----------------------------------------------------------------------------
__device__ __forceinline__ void grid_bar(unsigned &gen, int ncta) {
    __syncthreads();
    if (threadIdx.x == 0) {
        __threadfence();
        unsigned a = atomicAdd(&g_barCnt, 1u);
        if (a == (unsigned)(ncta - 1)) {
            g_barCnt = 0;
            __threadfence();
            atomicAdd(&g_barGen, 1u);
        } else {
            while (__ldcg(&g_barGen) <= gen) { __nanosleep(40); }
        }
    }
    gen++;
    __syncthreads();
}

// ----------------------------------------------------------------------------
// Generic C = act(A @ B^T + bias). A:[M,K], B:[N,K], row-major, K%16==0, M%64==0.
// 64x64 tile, 256 threads, 4x4 register microtile. Scalar FFMA (known 27.7TF/s).
// ACT: 0 none, 1 tanh, 2 relu
// ----------------------------------------------------------------------------
template<int ACT>
__global__ void __launch_bounds__(256)
gemm_tn(const float* __restrict__ A, const float* __restrict__ Bm,
        const float* __restrict__ bias, float* __restrict__ C,
        int M, int N, int K)
{
    __shared__ __align__(16) float As[16][64];
    __shared__ __align__(16) float Bs[16][64];
    const int m0 = blockIdx.x * 64;
    const int n0 = blockIdx.y * 64;
    const int tid = threadIdx.x;
    const int tr = tid >> 4;   // 0..15 -> rows tr*4..tr*4+3
    const int tc = tid & 15;   // 0..15 -> cols tc*4..tc*4+3

    float acc[4][4];
#pragma unroll
    for (int i = 0; i < 4; i++)
#pragma unroll
        for (int j = 0; j < 4; j++) acc[i][j] = 0.f;

    const int ml = tid >> 2;          // 0..63
    const int kq = (tid & 3) * 4;     // 0,4,8,12

    for (int k0 = 0; k0 < K; k0 += 16) {
        {
            float4 v = *(const float4*)(A + (size_t)(m0 + ml) * K + k0 + kq);
            As[kq+0][ml] = v.x; As[kq+1][ml] = v.y; As[kq+2][ml] = v.z; As[kq+3][ml] = v.w;
            float4 w = make_float4(0.f, 0.f, 0.f, 0.f);
            if (n0 + ml < N)
                w = *(const float4*)(Bm + (size_t)(n0 + ml) * K + k0 + kq);
            Bs[kq+0][ml] = w.x; Bs[kq+1][ml] = w.y; Bs[kq+2][ml] = w.z; Bs[kq+3][ml] = w.w;
        }
        __syncthreads();
#pragma unroll
        for (int kk = 0; kk < 16; kk++) {
            float4 a4 = *(const float4*)&As[kk][tr*4];
            float4 b4 = *(const float4*)&Bs[kk][tc*4];
            float av[4] = {a4.x, a4.y, a4.z, a4.w};
            float bv[4] = {b4.x, b4.y, b4.z, b4.w};
#pragma unroll
            for (int i = 0; i < 4; i++)
#pragma unroll
                for (int j = 0; j < 4; j++) acc[i][j] += av[i] * bv[j];
        }
        __syncthreads();
    }

#pragma unroll
    for (int j = 0; j < 4; j++) {
        int n = n0 + tc*4 + j;
        if (n >= N) continue;
        float bb = bias ? bias[n] : 0.f;
#pragma unroll
        for (int i = 0; i < 4; i++) {
            float v = acc[i][j] + bb;
            if (ACT == 1) v = tanhf(v);
            else if (ACT == 2) v = fmaxf(v, 0.f);
            C[(size_t)(m0 + tr*4 + i) * N + n] = v;
        }
    }
}

// ----------------------------------------------------------------------------
// Persistent LSTM layer: 128 CTAs (32 batch x 32 h tile), 512 threads (16
// warps/SM for latency hiding), all 50 timesteps in one launch with grid
// barriers. Whh slice cached in 64KB dynamic smem once; cell state in regs;
// cross-CTA h via __ldcg after fence+barrier.
// mode 0: h_buf laid out [b][t][H] (h_sb=T*H, t-offset t*H)
// mode 1: ping-pong      [t&1][b][H] (h_sb=H, t-offset (t&1)*B*H)
// ----------------------------------------------------------------------------
__global__ void __launch_bounds__(512)
lstm_persist(const float* __restrict__ xw,      // [B][T][G4]
             const float* __restrict__ Whh,     // [G4][ENC_H]
             const float* __restrict__ bih, const float* __restrict__ bhh,
             float* __restrict__ h_buf, int h_sb, int mode, int nsteps)
{
    extern __shared__ __align__(16) float Wsm[];  // [128 k][128 c] = 64KB
    __shared__ __align__(16) float As[ENC_H][33]; // [k][m], padded
    __shared__ float Gs[32][132];
    __shared__ float bsum[128];

    const int b0 = (blockIdx.x & 31) * 32;
    const int h0 = (blockIdx.x >> 5) * 32;
    const int tid = threadIdx.x;
    const int tr = tid >> 5;   // 0..15 -> rows 2*tr, 2*tr+1
    const int tc = tid & 31;   // cols tc*4..+3 of 128 gate-cols

    // one-time weight load: Wsm[k*128 + c] = Whh[jg(c)][k]
#pragma unroll
    for (int q = 0; q < 8; q++) {
        int e = tid + q * 512;            // 0..4095 (float4 units)
        int c = e & 127, kq = (e >> 7) * 4;
        int jg = (c >> 5) * ENC_H + h0 + (c & 31);
        float4 v = *(const float4*)(Whh + (size_t)jg * ENC_H + kq);
        Wsm[(kq+0)*128 + c] = v.x; Wsm[(kq+1)*128 + c] = v.y;
        Wsm[(kq+2)*128 + c] = v.z; Wsm[(kq+3)*128 + c] = v.w;
    }
    if (tid < 128) {
        int jg = (tid >> 5) * ENC_H + h0 + (tid & 31);
        bsum[tid] = bih[jg] + bhh[jg];
    }
    unsigned gen = __ldcg(&g_barGen);
    float creg[2] = {0.f, 0.f};
    __syncthreads();

    for (int t = 0; t < nsteps; t++) {
        float acc[2][4];
#pragma unroll
        for (int p = 0; p < 2; p++)
#pragma unroll
            for (int j = 0; j < 4; j++) acc[p][j] = 0.f;

        if (t > 0) {
            const float* hp = h_buf + (mode ? (size_t)((t-1) & 1) * BB * ENC_H
                                            : (size_t)(t-1) * ENC_H);
            // stage 32 rows x 128 k of h_prev (L2 via __ldcg)
#pragma unroll
            for (int q = 0; q < 2; q++) {
                int e = tid + q * 512;        // 0..1023 (float4 units)
                int m = e & 31, kq = (e >> 5) * 4;
                float4 v = __ldcg((const float4*)(hp + (size_t)(b0 + m) * h_sb + kq));
                As[kq+0][m] = v.x; As[kq+1][m] = v.y; As[kq+2][m] = v.z; As[kq+3][m] = v.w;
            }
            __syncthreads();
#pragma unroll 8
            for (int kk = 0; kk < ENC_H; kk++) {
                float a0 = As[kk][2*tr];          // warp-broadcast
                float a1 = As[kk][2*tr + 1];
                float4 w = *(const float4*)&Wsm[kk*128 + tc*4];
                acc[0][0] += a0 * w.x; acc[0][1] += a0 * w.y;
                acc[0][2] += a0 * w.z; acc[0][3] += a0 * w.w;
                acc[1][0] += a1 * w.x; acc[1][1] += a1 * w.y;
                acc[1][2] += a1 * w.z; acc[1][3] += a1 * w.w;
            }
        }

        // epilogue: gate pre-activations into Gs
#pragma unroll
        for (int j = 0; j < 4; j++) {
            int c = tc*4 + j;
            int jg = (c >> 5) * ENC_H + h0 + (c & 31);
            float bb = bsum[c];
#pragma unroll
            for (int p = 0; p < 2; p++) {
                int r = 2*tr + p;
                Gs[r][c] = acc[p][j]
                         + xw[(size_t)(b0 + r) * (T_HIST*G4) + (size_t)t * G4 + jg] + bb;
            }
        }
        __syncthreads();

        // gates + c/h update (c in registers: fixed (r,hh) per thread)
        float* ho = h_buf + (mode ? (size_t)(t & 1) * BB * ENC_H : (size_t)t * ENC_H);
#pragma unroll
        for (int q = 0; q < 2; q++) {
            int e = tid + q * 512;
            int r = e >> 5, hh = e & 31;
            float gi = Gs[r][hh];
            float gf = Gs[r][32 + hh];
            float gg = Gs[r][64 + hh];
            float go = Gs[r][96 + hh];
            float si = 1.f / (1.f + expf(-gi));
            float sf = 1.f / (1.f + expf(-gf));
            float so = 1.f / (1.f + expf(-go));
            float tg = tanhf(gg);
            float cn = sf * creg[q] + si * tg;
            creg[q] = cn;
            float hn = so * tanhf(cn);
            ho[(size_t)(b0 + r) * h_sb + h0 + hh] = hn;
        }
        if (t + 1 < nsteps) grid_bar(gen, (int)gridDim.x);
    }
}

// ----------------------------------------------------------------------------
// Fused CDE kernel: [optional] contract(stage sidx) -> k / z-update, then
// [optional] prep(next stage): stage combine + LayerNorm + relu(zn@W1^T+b1).
// Batch-row-local: CTA b owns rows b0..b0+31. grid = B/32, 256 threads.
// ----------------------------------------------------------------------------
__global__ void __launch_bounds__(256)
cde_fused(const float* __restrict__ coeffs,
          const float* __restrict__ gamma, const float* __restrict__ beta,
          const float* __restrict__ W1, const float* __restrict__ b1,
          int do_contract, int sidx, int idx, float u, int is_last,
          float c1, float c3, float c4, float c5, float c6,
          int do_prep, float a0, float a1, float a2, float a3, float a4, int nk)
{
    __shared__ __align__(16) float pool[8192];   // zs[32*65]+dX[32*33]; later W1s[64*128]
    __shared__ __align__(16) float znT[64][36];
    __shared__ float mu[32], rstd[32];
    float* zs  = pool;           // [r*65 + k]
    float* dXs = pool + 2080;    // [r*33 + ch]
    const int b0 = blockIdx.x * 32;
    const int tid = threadIdx.x;

    if (do_contract) {
        for (int e = tid; e < 32 * CHN; e += 256) {
            int r = e / CHN, ch = e - r * CHN;
            size_t base = ((size_t)(b0 + r) * 4 + idx) * (4 * CHN);
            float A1 = coeffs[base + CHN + ch];
            float A2 = coeffs[base + 2 * CHN + ch];
            float A3 = coeffs[base + 3 * CHN + ch];
            dXs[r * CHN + ch] = A1 + 2.f * A2 * u + 3.f * A3 * u * u;
        }
        __syncthreads();
        const float av[5] = {a0, a1, a2, a3, a4};
#pragma unroll
        for (int q = 0; q < 8; q++) {
            int e = tid + q * 256;
            int r = e >> 6, h = e & 63;
            const float* fr = g_f + (size_t)(b0 + r) * W2_ROWS + h * CHN;
            const float* dx = &dXs[r * CHN];
            float acc = 0.f;
#pragma unroll
            for (int ch = 0; ch < CHN; ch++) acc += fr[ch] * dx[ch];
            size_t gi = (size_t)(b0 + r) * CDE_H + h;
            if (is_last) {
                float z = g_z[gi] + c1 * g_k[0][gi] + c3 * g_k[2][gi]
                        + c4 * g_k[3][gi] + c5 * g_k[4][gi] + c6 * acc;
                g_z[gi] = z;
                zs[r * 65 + h] = z;
            } else {
                g_k[sidx][gi] = acc;
                float v = g_z[gi];
                for (int j = 0; j < nk; j++)
                    v += av[j] * ((j == sidx) ? acc : g_k[j][gi]);
                zs[r * 65 + h] = v;
            }
        }
    } else {
#pragma unroll
        for (int q = 0; q < 8; q++) {
            int e = tid + q * 256;
            int r = e >> 6, h = e & 63;
            zs[r * 65 + h] = g_z[(size_t)(b0 + r) * CDE_H + h];
        }
    }
    if (!do_prep) return;
    __syncthreads();

    // LayerNorm stats: 8 lanes per row, two-pass, butterfly reduce
    {
        int row = tid >> 3, lane = tid & 7;
        float s = 0.f;
        for (int k = lane; k < 64; k += 8) s += zs[row * 65 + k];
#pragma unroll
        for (int d = 1; d < 8; d <<= 1) s += __shfl_xor_sync(0xffffffffu, s, d, 8);
        float m = s * (1.f / 64.f);
        float q2 = 0.f;
        for (int k = lane; k < 64; k += 8) { float dd = zs[row * 65 + k] - m; q2 += dd * dd; }
#pragma unroll
        for (int d = 1; d < 8; d <<= 1) q2 += __shfl_xor_sync(0xffffffffu, q2, d, 8);
        if (lane == 0) { mu[row] = m; rstd[row] = rsqrtf(q2 * (1.f / 64.f) + 1e-5f); }
    }
    __syncthreads();
#pragma unroll
    for (int q = 0; q < 8; q++) {
        int e = tid + q * 256;
        int k = e >> 5, r = e & 31;
        znT[k][r] = (zs[r * 65 + k] - mu[r]) * rstd[r] * gamma[k] + beta[k];
    }
    __syncthreads();

    // W1 transposed into pool (overwrites zs/dXs)
    float* W1s = pool;
#pragma unroll
    for (int q = 0; q < 32; q++) {
        int e = tid + q * 256;               // 0..8191
        int j = e >> 6, k = e & 63;
        W1s[k * 128 + j] = W1[e];
    }
    __syncthreads();

    const int tr = tid >> 5;   // rows tr*4
    const int tc = tid & 31;   // cols tc*4 of 128
    float acc[4][4];
#pragma unroll
    for (int i = 0; i < 4; i++)
#pragma unroll
        for (int j = 0; j < 4; j++) acc[i][j] = 0.f;
#pragma unroll 4
    for (int k = 0; k < 64; k++) {
        float zf[4];
#pragma unroll
        for (int i = 0; i < 4; i++) zf[i] = znT[k][tr*4 + i];
        float4 w4 = *(const float4*)&W1s[k * 128 + tc*4];
        float wv[4] = {w4.x, w4.y, w4.z, w4.w};
#pragma unroll
        for (int i = 0; i < 4; i++)
#pragma unroll
            for (int j = 0; j < 4; j++) acc[i][j] += zf[i] * wv[j];
    }
#pragma unroll
    for (int j = 0; j < 4; j++) {
        int col = tc*4 + j;
        float bb = b1[col];
#pragma unroll
        for (int i = 0; i < 4; i++) {
            g_a[(size_t)(b0 + tr*4 + i) * MLP_H + col] = fmaxf(acc[i][j] + bb, 0.f);
        }
    }
}

// ----------------------------------------------------------------------------
// Host orchestration
// ----------------------------------------------------------------------------
extern "C" void kernel_launch(void* const* d_in, const int* in_sizes, int n_in,
                              void* d_out, int out_size)
{
    const float* hist   = (const float*)d_in[0];
    const float* coeffs = (const float*)d_in[1];
    // d_in[2] = cde_times = [0,1] (deterministic; baked in)
    const float* W_ih0 = (const float*)d_in[3];
    const float* W_hh0 = (const float*)d_in[4];
    const float* b_ih0 = (const float*)d_in[5];
    const float* b_hh0 = (const float*)d_in[6];
    const float* W_ih1 = (const float*)d_in[7];
    const float* W_hh1 = (const float*)d_in[8];
    const float* b_ih1 = (const float*)d_in[9];
    const float* b_hh1 = (const float*)d_in[10];
    const float* W_map = (const float*)d_in[11];
    const float* b_map = (const float*)d_in[12];
    const float* gamma = (const float*)d_in[13];
    const float* beta  = (const float*)d_in[14];
    const float* W1    = (const float*)d_in[15];
    const float* b1    = (const float*)d_in[16];
    const float* W2    = (const float*)d_in[17];
    const float* b2    = (const float*)d_in[18];
    const float* W_pred = (const float*)d_in[19];
    const float* b_pred = (const float*)d_in[20];
    float* out = (float*)d_out;

    float *p_xW, *p_seq0, *p_h1, *p_z, *p_a, *p_f;
    cudaGetSymbolAddress((void**)&p_xW,   g_xW);
    cudaGetSymbolAddress((void**)&p_seq0, g_seq0);
    cudaGetSymbolAddress((void**)&p_h1,   g_h1);
    cudaGetSymbolAddress((void**)&p_z,    g_z);
    cudaGetSymbolAddress((void**)&p_a,    g_a);
    cudaGetSymbolAddress((void**)&p_f,    g_f);

    const int WSM_BYTES = 128 * 128 * 4;   // 64KB dynamic smem for Whh slice
    cudaFuncSetAttribute(lstm_persist, cudaFuncAttributeMaxDynamicSharedMemorySize, WSM_BYTES);

    // ---------------- LSTM layer 0 ----------------
    gemm_tn<0><<<dim3(BB*T_HIST/64, G4/64), 256>>>(hist, W_ih0, nullptr, p_xW,
                                                   BB*T_HIST, G4, ENC_IN);
    lstm_persist<<<128, 512, WSM_BYTES>>>(p_xW, W_hh0, b_ih0, b_hh0,
                                          p_seq0, T_HIST*ENC_H, 0, T_HIST);

    // ---------------- LSTM layer 1 ----------------
    gemm_tn<0><<<dim3(BB*T_HIST/64, G4/64), 256>>>(p_seq0, W_ih1, nullptr, p_xW,
                                                   BB*T_HIST, G4, ENC_H);
    lstm_persist<<<128, 512, WSM_BYTES>>>(p_xW, W_hh1, b_ih1, b_hh1,
                                          p_h1, ENC_H, 1, T_HIST);
    const float* context = p_h1 + (size_t)((T_HIST - 1) & 1) * BB * ENC_H;

    // ---------------- map to z0 ----------------
    gemm_tn<1><<<dim3(BB/64, 1), 256>>>(context, W_map, b_map, p_z, BB, CDE_H, ENC_H);

    // ---------------- Neural CDE, RK45 (Dormand-Prince) ----------------
    const double dt = 1.0 / N_STEPS;
    const double ACF[6][5] = {
        {0, 0, 0, 0, 0},
        {1.0/5, 0, 0, 0, 0},
        {3.0/40, 9.0/40, 0, 0, 0},
        {44.0/45, -56.0/15, 32.0/9, 0, 0},
        {19372.0/6561, -25360.0/2187, 64448.0/6561, -212.0/729, 0},
        {9017.0/3168, -355.0/33, 46732.0/5247, 49.0/176, -5103.0/18656}
    };
    const double COFF[6] = {0.0, 1.0/5, 3.0/10, 4.0/5, 8.0/9, 1.0};
    const double BU[5] = {35.0/384, 500.0/1113, 125.0/192, -2187.0/6784, 11.0/84};

    // initial prep (step 0, stage 0): no contract, nk=0
    cde_fused<<<BB/32, 256>>>(coeffs, gamma, beta, W1, b1,
        0, 0, 0, 0.f, 0, 0.f, 0.f, 0.f, 0.f, 0.f,
        1, 0.f, 0.f, 0.f, 0.f, 0.f, 0);

    for (int i = 0; i < N_STEPS; i++) {
        for (int s = 0; s < 6; s++) {
            gemm_tn<1><<<dim3(BB/64, W2_ROWS/64), 256>>>(p_a, W2, b2, p_f,
                                                         BB, W2_ROWS, MLP_H);
            float ts = (float)((i + COFF[s]) * dt);
            int idx = (int)floorf(ts / 0.25f);
            if (idx < 0) idx = 0;
            if (idx > 3) idx = 3;
            float u = ts - (float)idx * 0.25f;

            int last = (s == 5);
            int do_prep = !(i == N_STEPS - 1 && s == 5);
            int nk = last ? 0 : (s + 1);
            const double* ar = last ? ACF[0] : ACF[s + 1];

            cde_fused<<<BB/32, 256>>>(coeffs, gamma, beta, W1, b1,
                1, s, idx, u, last,
                (float)(dt*BU[0]), (float)(dt*BU[1]), (float)(dt*BU[2]),
                (float)(dt*BU[3]), (float)(dt*BU[4]),
                do_prep,
                (float)(dt*ar[0]), (float)(dt*ar[1]), (float)(dt*ar[2]),
                (float)(dt*ar[3]), (float)(dt*ar[4]), nk);
        }
    }

    // ---------------- final projection ----------------
    gemm_tn<0><<<dim3(BB/64, (NZ + 63)/64), 256>>>(p_z, W_pred, b_pred, out,
                                                   BB, NZ, CDE_H);
}

// round 10
// speedup vs baseline: 2.2831x; 1.4505x over previous
#include <cuda_runtime.h>
#include <cuda_bf16.h>

#define BB 1024
#define T_HIST 50
#define ENC_IN 96
#define ENC_H 128
#define G4 (4*ENC_H)          // 512
#define CDE_H 64
#define CHN 33
#define NZ 10000
#define MLP_H 128
#define W2_ROWS (CHN*CDE_H)   // 2112
#define N_STEPS 16

// ----------------------------------------------------------------------------
// Scratch (static device globals — no allocation)
// ----------------------------------------------------------------------------
__device__ float g_xW[BB*T_HIST*G4];
__device__ float g_seq0[BB*T_HIST*ENC_H];
__device__ float g_h1[2][BB*ENC_H];
__device__ float g_z[BB*CDE_H];
__device__ float g_k[6][BB*CDE_H];
__device__ float g_a[BB*MLP_H];
__device__ float g_f[BB*W2_ROWS];

__device__ unsigned g_barGen;
__device__ unsigned g_barCnt;

// ----------------------------------------------------------------------------
// Grid-wide barrier (persistent LSTM). Poll via plain L2 load, not atomics.
// ----------------------------------------------------------------------------
__device__ __forceinline__ void grid_bar(unsigned &gen, int ncta) {
    __syncthreads();
    if (threadIdx.x == 0) {
        __threadfence();
        unsigned a = atomicAdd(&g_barCnt, 1u);
        if (a == (unsigned)(ncta - 1)) {
            g_barCnt = 0;
            __threadfence();
            atomicAdd(&g_barGen, 1u);
        } else {
            while (__ldcg(&g_barGen) <= gen) { __nanosleep(40); }
        }
    }
    gen++;
    __syncthreads();
}

// ----------------------------------------------------------------------------
// tf32 helpers (portable PTX, sm_80+; no tcgen05 — ptxas here targets sm_103)
// ----------------------------------------------------------------------------
__device__ __forceinline__ unsigned f2tf32(float v) {
    unsigned r;
    asm("cvt.rna.tf32.f32 %0, %1;" : "=r"(r) : "f"(v));
    return r;
}
__device__ __forceinline__ void mma_tf32(float c[4], uint4 a, uint2 b) {
    asm volatile(
        "mma.sync.aligned.m16n8k8.row.col.f32.tf32.tf32.f32 "
        "{%0,%1,%2,%3}, {%4,%5,%6,%7}, {%8,%9}, {%0,%1,%2,%3};"
        : "+f"(c[0]), "+f"(c[1]), "+f"(c[2]), "+f"(c[3])
        : "r"(a.x), "r"(a.y), "r"(a.z), "r"(a.w), "r"(b.x), "r"(b.y));
}

// ----------------------------------------------------------------------------
// Tensor-core W2 GEMM via 3xTF32 mma.sync: f = tanh(a @ W2^T + b2).
// A: g_a [1024][128] f32. W2: [2112][128] f32. CTA tile 128x64, 256 thr
// (8 warps, warp tile 32x32), K chunked by 32. Operands staged in smem in
// FRAGMENT ORDER (scatter on store -> ld.shared.v4/v2 on load).
// Layout, per K-chunk (4 ksteps of 8):
//   A_s[((kstep*8 + mtile)*2 + hl)*128 + lane*4 + slot]   (8192 u32)
//     slot = (row16>=8) | ((k8>=4)<<1); lane = (row16&7)*4 + (k8&3)
//   B_s[((kstep*8 + ntile)*2 + hl)*64 + lane*2 + slot]    (4096 u32)
//     slot = (k8>=4);  lane = (n&7)*4 + (k8&3)
// ----------------------------------------------------------------------------
__global__ void __launch_bounds__(256)
gemm_w2_tc(const float* __restrict__ A, const float* __restrict__ W2,
           const float* __restrict__ b2, float* __restrict__ Fout)
{
    extern __shared__ unsigned pool[];          // 12288 u32 = 48KB
    unsigned* As = pool;                        // 8192
    unsigned* Bs = pool + 8192;                 // 4096
    const int tid = threadIdx.x;
    const int w = tid >> 5, l = tid & 31;
    const int wm = w & 3, wn = w >> 2;          // 4 m-warps x 2 n-warps
    const int m0 = blockIdx.x * 128, n0 = blockIdx.y * 64;

    float acc[2][4][4];
#pragma unroll
    for (int mt = 0; mt < 2; mt++)
#pragma unroll
        for (int nt = 0; nt < 4; nt++)
#pragma unroll
            for (int i = 0; i < 4; i++) acc[mt][nt][i] = 0.f;

    for (int ch = 0; ch < 4; ch++) {
        const int k0 = ch * 32;
        if (ch) __syncthreads();                // protect pool from prior reads

        // stage A chunk (128 rows x 32 k), fragment-order scatter
#pragma unroll
        for (int q = 0; q < 16; q++) {
            int e = tid + q * 256;              // 0..4095
            int r = e >> 5, kk = e & 31;
            float v = A[(size_t)(m0 + r) * 128 + k0 + kk];
            unsigned hb = f2tf32(v);
            unsigned lb = f2tf32(v - __uint_as_float(hb));
            int kstep = kk >> 3, k8 = kk & 7;
            int mtile = r >> 4, r16 = r & 15;
            int lane = (r16 & 7) * 4 + (k8 & 3);
            int slot = ((r16 >> 3) & 1) | ((k8 >> 2) << 1);
            int base = ((kstep * 8 + mtile) * 2) * 128 + lane * 4 + slot;
            As[base] = hb;
            As[base + 128] = lb;
        }
        // stage B chunk (64 rows x 32 k)
#pragma unroll
        for (int q = 0; q < 8; q++) {
            int e = tid + q * 256;              // 0..2047
            int n = e >> 5, kk = e & 31;
            float v = W2[(size_t)(n0 + n) * 128 + k0 + kk];
            unsigned hb = f2tf32(v);
            unsigned lb = f2tf32(v - __uint_as_float(hb));
            int kstep = kk >> 3, k8 = kk & 7;
            int ntile = n >> 3;
            int lane = (n & 7) * 4 + (k8 & 3);
            int slot = (k8 >> 2) & 1;
            int base = ((kstep * 8 + ntile) * 2) * 64 + lane * 2 + slot;
            Bs[base] = hb;
            Bs[base + 64] = lb;
        }
        __syncthreads();

#pragma unroll
        for (int kstep = 0; kstep < 4; kstep++) {
            uint4 Ahi[2], Alo[2];
            uint2 Bhi[4], Blo[4];
#pragma unroll
            for (int mt = 0; mt < 2; mt++) {
                int mtile = wm * 2 + mt;
                int base = ((kstep * 8 + mtile) * 2) * 128 + l * 4;
                Ahi[mt] = *(const uint4*)&As[base];
                Alo[mt] = *(const uint4*)&As[base + 128];
            }
#pragma unroll
            for (int nt = 0; nt < 4; nt++) {
                int ntile = wn * 4 + nt;
                int base = ((kstep * 8 + ntile) * 2) * 64 + l * 2;
                Bhi[nt] = *(const uint2*)&Bs[base];
                Blo[nt] = *(const uint2*)&Bs[base + 64];
            }
#pragma unroll
            for (int mt = 0; mt < 2; mt++)
#pragma unroll
                for (int nt = 0; nt < 4; nt++) {
                    mma_tf32(acc[mt][nt], Ahi[mt], Bhi[nt]);
                    mma_tf32(acc[mt][nt], Ahi[mt], Blo[nt]);
                    mma_tf32(acc[mt][nt], Alo[mt], Bhi[nt]);
                }
        }
    }

    // epilogue: fragments -> padded smem -> coalesced float4 stores
    __syncthreads();
    float* S = (float*)pool;                    // 128 x 68 = 8704 <= 12288
    const int g = l >> 2, tq = l & 3;
#pragma unroll
    for (int mt = 0; mt < 2; mt++)
#pragma unroll
        for (int nt = 0; nt < 4; nt++) {
            int row = wm * 32 + mt * 16 + g;
            int col = wn * 32 + nt * 8 + tq * 2;
            S[row * 68 + col]           = acc[mt][nt][0];
            S[row * 68 + col + 1]       = acc[mt][nt][1];
            S[(row + 8) * 68 + col]     = acc[mt][nt][2];
            S[(row + 8) * 68 + col + 1] = acc[mt][nt][3];
        }
    __syncthreads();
#pragma unroll
    for (int q = 0; q < 8; q++) {
        int e = tid + q * 256;                  // 0..2047 (float4 units)
        int r = e >> 4, c4 = (e & 15) * 4;
        float4 v = *(const float4*)&S[r * 68 + c4];
        float4 o;
        o.x = tanhf(v.x + b2[n0 + c4 + 0]);
        o.y = tanhf(v.y + b2[n0 + c4 + 1]);
        o.z = tanhf(v.z + b2[n0 + c4 + 2]);
        o.w = tanhf(v.w + b2[n0 + c4 + 3]);
        *(float4*)&Fout[(size_t)(m0 + r) * W2_ROWS + n0 + c4] = o;
    }
}

// ----------------------------------------------------------------------------
// Generic C = act(A @ B^T + bias). Scalar FFMA (27.7 TF/s measured).
// ----------------------------------------------------------------------------
template<int ACT>
__global__ void __launch_bounds__(256)
gemm_tn(const float* __restrict__ A, const float* __restrict__ Bm,
        const float* __restrict__ bias, float* __restrict__ C,
        int M, int N, int K)
{
    __shared__ __align__(16) float As[16][64];
    __shared__ __align__(16) float Bs[16][64];
    const int m0 = blockIdx.x * 64;
    const int n0 = blockIdx.y * 64;
    const int tid = threadIdx.x;
    const int tr = tid >> 4;
    const int tc = tid & 15;

    float acc[4][4];
#pragma unroll
    for (int i = 0; i < 4; i++)
#pragma unroll
        for (int j = 0; j < 4; j++) acc[i][j] = 0.f;

    const int ml = tid >> 2;
    const int kq = (tid & 3) * 4;

    for (int k0 = 0; k0 < K; k0 += 16) {
        {
            float4 v = *(const float4*)(A + (size_t)(m0 + ml) * K + k0 + kq);
            As[kq+0][ml] = v.x; As[kq+1][ml] = v.y; As[kq+2][ml] = v.z; As[kq+3][ml] = v.w;
            float4 w = make_float4(0.f, 0.f, 0.f, 0.f);
            if (n0 + ml < N)
                w = *(const float4*)(Bm + (size_t)(n0 + ml) * K + k0 + kq);
            Bs[kq+0][ml] = w.x; Bs[kq+1][ml] = w.y; Bs[kq+2][ml] = w.z; Bs[kq+3][ml] = w.w;
        }
        __syncthreads();
#pragma unroll
        for (int kk = 0; kk < 16; kk++) {
            float4 a4 = *(const float4*)&As[kk][tr*4];
            float4 b4 = *(const float4*)&Bs[kk][tc*4];
            float av[4] = {a4.x, a4.y, a4.z, a4.w};
            float bv[4] = {b4.x, b4.y, b4.z, b4.w};
#pragma unroll
            for (int i = 0; i < 4; i++)
#pragma unroll
                for (int j = 0; j < 4; j++) acc[i][j] += av[i] * bv[j];
        }
        __syncthreads();
    }

#pragma unroll
    for (int j = 0; j < 4; j++) {
        int n = n0 + tc*4 + j;
        if (n >= N) continue;
        float bb = bias ? bias[n] : 0.f;
#pragma unroll
        for (int i = 0; i < 4; i++) {
            float v = acc[i][j] + bb;
            if (ACT == 1) v = tanhf(v);
            else if (ACT == 2) v = fmaxf(v, 0.f);
            C[(size_t)(m0 + tr*4 + i) * N + n] = v;
        }
    }
}

// ----------------------------------------------------------------------------
// Persistent LSTM layer (512 threads, 128 CTAs) — round-7 version (508us/layer)
// ----------------------------------------------------------------------------
__global__ void __launch_bounds__(512)
lstm_persist(const float* __restrict__ xw,
             const float* __restrict__ Whh,
             const float* __restrict__ bih, const float* __restrict__ bhh,
             float* __restrict__ h_buf, int h_sb, int mode, int nsteps)
{
    extern __shared__ __align__(16) float Wsm[];
    __shared__ __align__(16) float As[ENC_H][33];
    __shared__ float Gs[32][132];
    __shared__ float bsum[128];

    const int b0 = (blockIdx.x & 31) * 32;
    const int h0 = (blockIdx.x >> 5) * 32;
    const int tid = threadIdx.x;
    const int tr = tid >> 5;
    const int tc = tid & 31;

#pragma unroll
    for (int q = 0; q < 8; q++) {
        int e = tid + q * 512;
        int c = e & 127, kq = (e >> 7) * 4;
        int jg = (c >> 5) * ENC_H + h0 + (c & 31);
        float4 v = *(const float4*)(Whh + (size_t)jg * ENC_H + kq);
        Wsm[(kq+0)*128 + c] = v.x; Wsm[(kq+1)*128 + c] = v.y;
        Wsm[(kq+2)*128 + c] = v.z; Wsm[(kq+3)*128 + c] = v.w;
    }
    if (tid < 128) {
        int jg = (tid >> 5) * ENC_H + h0 + (tid & 31);
        bsum[tid] = bih[jg] + bhh[jg];
    }
    unsigned gen = __ldcg(&g_barGen);
    float creg[2] = {0.f, 0.f};
    __syncthreads();

    for (int t = 0; t < nsteps; t++) {
        float acc[2][4];
#pragma unroll
        for (int p = 0; p < 2; p++)
#pragma unroll
            for (int j = 0; j < 4; j++) acc[p][j] = 0.f;

        if (t > 0) {
            const float* hp = h_buf + (mode ? (size_t)((t-1) & 1) * BB * ENC_H
                                            : (size_t)(t-1) * ENC_H);
#pragma unroll
            for (int q = 0; q < 2; q++) {
                int e = tid + q * 512;
                int m = e & 31, kq = (e >> 5) * 4;
                float4 v = __ldcg((const float4*)(hp + (size_t)(b0 + m) * h_sb + kq));
                As[kq+0][m] = v.x; As[kq+1][m] = v.y; As[kq+2][m] = v.z; As[kq+3][m] = v.w;
            }
            __syncthreads();
#pragma unroll 8
            for (int kk = 0; kk < ENC_H; kk++) {
                float a0 = As[kk][2*tr];
                float a1 = As[kk][2*tr + 1];
                float4 w = *(const float4*)&Wsm[kk*128 + tc*4];
                acc[0][0] += a0 * w.x; acc[0][1] += a0 * w.y;
                acc[0][2] += a0 * w.z; acc[0][3] += a0 * w.w;
                acc[1][0] += a1 * w.x; acc[1][1] += a1 * w.y;
                acc[1][2] += a1 * w.z; acc[1][3] += a1 * w.w;
            }
        }

#pragma unroll
        for (int j = 0; j < 4; j++) {
            int c = tc*4 + j;
            int jg = (c >> 5) * ENC_H + h0 + (c & 31);
            float bb = bsum[c];
#pragma unroll
            for (int p = 0; p < 2; p++) {
                int r = 2*tr + p;
                Gs[r][c] = acc[p][j]
                         + xw[(size_t)(b0 + r) * (T_HIST*G4) + (size_t)t * G4 + jg] + bb;
            }
        }
        __syncthreads();

        float* ho = h_buf + (mode ? (size_t)(t & 1) * BB * ENC_H : (size_t)t * ENC_H);
#pragma unroll
        for (int q = 0; q < 2; q++) {
            int e = tid + q * 512;
            int r = e >> 5, hh = e & 31;
            float gi = Gs[r][hh];
            float gf = Gs[r][32 + hh];
            float gg = Gs[r][64 + hh];
            float go = Gs[r][96 + hh];
            float si = 1.f / (1.f + expf(-gi));
            float sf = 1.f / (1.f + expf(-gf));
            float so = 1.f / (1.f + expf(-go));
            float tg = tanhf(gg);
            float cn = sf * creg[q] + si * tg;
            creg[q] = cn;
            float hn = so * tanhf(cn);
            ho[(size_t)(b0 + r) * h_sb + h0 + hh] = hn;
        }
        if (t + 1 < nsteps) grid_bar(gen, (int)gridDim.x);
    }
}

// ----------------------------------------------------------------------------
// CDE stage prep: zs = z + sum a_j k_j; LayerNorm; a = relu(zn@W1^T + b1).
// grid = B/32, 256 threads. (Round-4 verified version.)
// ----------------------------------------------------------------------------
__global__ void __launch_bounds__(256)
cde_prep(const float* __restrict__ gamma, const float* __restrict__ beta,
         const float* __restrict__ W1, const float* __restrict__ b1,
         float a0, float a1, float a2, float a3, float a4, int nk)
{
    __shared__ __align__(16) float znT[64][36];
    __shared__ __align__(16) float pool[8192];
    __shared__ float mu[32], rstd[32];
    const int b0 = blockIdx.x * 32;
    const int tid = threadIdx.x;
    const float av[5] = {a0, a1, a2, a3, a4};
    float* zs = pool;

#pragma unroll
    for (int q = 0; q < 8; q++) {
        int e = tid + q * 256;
        int r = e >> 6, k = e & 63;
        size_t gi = (size_t)(b0 + r) * CDE_H + k;
        float v = g_z[gi];
        for (int j = 0; j < nk; j++) v += av[j] * g_k[j][gi];
        zs[r * 65 + k] = v;
    }
    __syncthreads();
    {
        int row = tid >> 3, lane = tid & 7;
        float s = 0.f;
        for (int k = lane; k < 64; k += 8) s += zs[row * 65 + k];
#pragma unroll
        for (int d = 1; d < 8; d <<= 1) s += __shfl_xor_sync(0xffffffffu, s, d, 8);
        float m = s * (1.f / 64.f);
        float q2 = 0.f;
        for (int k = lane; k < 64; k += 8) { float dd = zs[row * 65 + k] - m; q2 += dd * dd; }
#pragma unroll
        for (int d = 1; d < 8; d <<= 1) q2 += __shfl_xor_sync(0xffffffffu, q2, d, 8);
        if (lane == 0) { mu[row] = m; rstd[row] = rsqrtf(q2 * (1.f / 64.f) + 1e-5f); }
    }
    __syncthreads();
#pragma unroll
    for (int q = 0; q < 8; q++) {
        int e = tid + q * 256;
        int k = e >> 5, r = e & 31;
        znT[k][r] = (zs[r * 65 + k] - mu[r]) * rstd[r] * gamma[k] + beta[k];
    }
    __syncthreads();

    float* W1s = pool;
#pragma unroll
    for (int q = 0; q < 32; q++) {
        int e = tid + q * 256;
        int j = e >> 6, k = e & 63;
        W1s[k * 128 + j] = W1[e];
    }
    __syncthreads();

    const int tr = tid >> 5;
    const int tc = tid & 31;
    float acc[4][4];
#pragma unroll
    for (int i = 0; i < 4; i++)
#pragma unroll
        for (int j = 0; j < 4; j++) acc[i][j] = 0.f;
#pragma unroll 4
    for (int k = 0; k < 64; k++) {
        float zf[4];
#pragma unroll
        for (int i = 0; i < 4; i++) zf[i] = znT[k][tr*4 + i];
        float4 w4 = *(const float4*)&W1s[k * 128 + tc*4];
        float wv[4] = {w4.x, w4.y, w4.z, w4.w};
#pragma unroll
        for (int i = 0; i < 4; i++)
#pragma unroll
            for (int j = 0; j < 4; j++) acc[i][j] += zf[i] * wv[j];
    }
#pragma unroll
    for (int j = 0; j < 4; j++) {
        int col = tc*4 + j;
        float bb = b1[col];
#pragma unroll
        for (int i = 0; i < 4; i++) {
            g_a[(size_t)(b0 + tr*4 + i) * MLP_H + col] = fmaxf(acc[i][j] + bb, 0.f);
        }
    }
}

// ----------------------------------------------------------------------------
// Contract: k_s = sum_ch f * dX; stage 6 applies DP45 z-update.
// grid = B blocks, 64 threads. (Round-4 verified version.)
// ----------------------------------------------------------------------------
__global__ void __launch_bounds__(64)
cde_contract(const float* __restrict__ coeffs, int sidx, int idx, float u,
             int do_update, float c1, float c3, float c4, float c5, float c6)
{
    __shared__ float dX[CHN];
    const int b = blockIdx.x;
    const int tid = threadIdx.x;
    if (tid < CHN) {
        size_t base = ((size_t)b * 4 + idx) * 4 * CHN;
        float A1 = coeffs[base + 1 * CHN + tid];
        float A2 = coeffs[base + 2 * CHN + tid];
        float A3 = coeffs[base + 3 * CHN + tid];
        dX[tid] = A1 + 2.f * A2 * u + 3.f * A3 * u * u;
    }
    __syncthreads();
    const float* fr = g_f + (size_t)b * W2_ROWS + tid * CHN;
    float acc = 0.f;
#pragma unroll
    for (int ch = 0; ch < CHN; ch++) acc += fr[ch] * dX[ch];
    size_t gi = (size_t)b * CDE_H + tid;
    g_k[sidx][gi] = acc;
    if (do_update) {
        g_z[gi] += c1 * g_k[0][gi] + c3 * g_k[2][gi] + c4 * g_k[3][gi]
                 + c5 * g_k[4][gi] + c6 * acc;
    }
}

// ----------------------------------------------------------------------------
// Host orchestration
// ----------------------------------------------------------------------------
extern "C" void kernel_launch(void* const* d_in, const int* in_sizes, int n_in,
                              void* d_out, int out_size)
{
    const float* hist   = (const float*)d_in[0];
    const float* coeffs = (const float*)d_in[1];
    const float* W_ih0 = (const float*)d_in[3];
    const float* W_hh0 = (const float*)d_in[4];
    const float* b_ih0 = (const float*)d_in[5];
    const float* b_hh0 = (const float*)d_in[6];
    const float* W_ih1 = (const float*)d_in[7];
    const float* W_hh1 = (const float*)d_in[8];
    const float* b_ih1 = (const float*)d_in[9];
    const float* b_hh1 = (const float*)d_in[10];
    const float* W_map = (const float*)d_in[11];
    const float* b_map = (const float*)d_in[12];
    const float* gamma = (const float*)d_in[13];
    const float* beta  = (const float*)d_in[14];
    const float* W1    = (const float*)d_in[15];
    const float* b1    = (const float*)d_in[16];
    const float* W2    = (const float*)d_in[17];
    const float* b2    = (const float*)d_in[18];
    const float* W_pred = (const float*)d_in[19];
    const float* b_pred = (const float*)d_in[20];
    float* out = (float*)d_out;

    float *p_xW, *p_seq0, *p_h1, *p_z, *p_a, *p_f;
    cudaGetSymbolAddress((void**)&p_xW,   g_xW);
    cudaGetSymbolAddress((void**)&p_seq0, g_seq0);
    cudaGetSymbolAddress((void**)&p_h1,   g_h1);
    cudaGetSymbolAddress((void**)&p_z,    g_z);
    cudaGetSymbolAddress((void**)&p_a,    g_a);
    cudaGetSymbolAddress((void**)&p_f,    g_f);

    const int WSM_BYTES = 128 * 128 * 4;
    const int TC_SMEM = 12288 * 4;          // 48KB dynamic
    cudaFuncSetAttribute(lstm_persist, cudaFuncAttributeMaxDynamicSharedMemorySize, WSM_BYTES);
    cudaFuncSetAttribute(gemm_w2_tc, cudaFuncAttributeMaxDynamicSharedMemorySize, TC_SMEM);

    // ---------------- LSTM layer 0 ----------------
    gemm_tn<0><<<dim3(BB*T_HIST/64, G4/64), 256>>>(hist, W_ih0, nullptr, p_xW,
                                                   BB*T_HIST, G4, ENC_IN);
    lstm_persist<<<128, 512, WSM_BYTES>>>(p_xW, W_hh0, b_ih0, b_hh0,
                                          p_seq0, T_HIST*ENC_H, 0, T_HIST);

    // ---------------- LSTM layer 1 ----------------
    gemm_tn<0><<<dim3(BB*T_HIST/64, G4/64), 256>>>(p_seq0, W_ih1, nullptr, p_xW,
                                                   BB*T_HIST, G4, ENC_H);
    lstm_persist<<<128, 512, WSM_BYTES>>>(p_xW, W_hh1, b_ih1, b_hh1,
                                          p_h1, ENC_H, 1, T_HIST);
    const float* context = p_h1 + (size_t)((T_HIST - 1) & 1) * BB * ENC_H;

    // ---------------- map to z0 ----------------
    gemm_tn<1><<<dim3(BB/64, 1), 256>>>(context, W_map, b_map, p_z, BB, CDE_H, ENC_H);

    // ---------------- Neural CDE, RK45 (Dormand-Prince) ----------------
    const double dt = 1.0 / N_STEPS;
    const double ACF[6][5] = {
        {0, 0, 0, 0, 0},
        {1.0/5, 0, 0, 0, 0},
        {3.0/40, 9.0/40, 0, 0, 0},
        {44.0/45, -56.0/15, 32.0/9, 0, 0},
        {19372.0/6561, -25360.0/2187, 64448.0/6561, -212.0/729, 0},
        {9017.0/3168, -355.0/33, 46732.0/5247, 49.0/176, -5103.0/18656}
    };
    const double COFF[6] = {0.0, 1.0/5, 3.0/10, 4.0/5, 8.0/9, 1.0};
    const double BU[5] = {35.0/384, 500.0/1113, 125.0/192, -2187.0/6784, 11.0/84};

    for (int i = 0; i < N_STEPS; i++) {
        float t = (float)(i * dt);
        for (int s = 0; s < 6; s++) {
            cde_prep<<<BB/32, 256>>>(gamma, beta, W1, b1,
                (float)(dt*ACF[s][0]), (float)(dt*ACF[s][1]), (float)(dt*ACF[s][2]),
                (float)(dt*ACF[s][3]), (float)(dt*ACF[s][4]), s);

            gemm_w2_tc<<<dim3(BB/128, W2_ROWS/64), 256, TC_SMEM>>>(p_a, W2, b2, p_f);

            float ts = t + (float)(dt * COFF[s]);
            int idx = (int)floorf(ts / 0.25f);
            if (idx < 0) idx = 0;
            if (idx > 3) idx = 3;
            float u = ts - (float)idx * 0.25f;
            cde_contract<<<BB, CDE_H>>>(coeffs, s, idx, u, (s == 5) ? 1 : 0,
                (float)(dt*BU[0]), (float)(dt*BU[1]), (float)(dt*BU[2]),
                (float)(dt*BU[3]), (float)(dt*BU[4]));
        }
    }

    // ---------------- final projection ----------------
    gemm_tn<0><<<dim3(BB/64, (NZ + 63)/64), 256>>>(p_z, W_pred, b_pred, out,
                                                   BB, NZ, CDE_H);
}

// round 11
// speedup vs baseline: 2.3808x; 1.0428x over previous
#include <cuda_runtime.h>
#include <cuda_bf16.h>

#define BB 1024
#define T_HIST 50
#define ENC_IN 96
#define ENC_H 128
#define G4 (4*ENC_H)          // 512
#define CDE_H 64
#define CHN 33
#define NZ 10000
#define MLP_H 128
#define W2_ROWS (CHN*CDE_H)   // 2112
#define N_STEPS 16

// ----------------------------------------------------------------------------
// Scratch (static device globals — no allocation)
// ----------------------------------------------------------------------------
__device__ float g_xW[BB*T_HIST*G4];
__device__ float g_seq0[BB*T_HIST*ENC_H];
__device__ float g_h1[2][BB*ENC_H];
__device__ float g_z[BB*CDE_H];
__device__ float g_k[6][BB*CDE_H];
__device__ float g_f[BB*W2_ROWS];

// tf32 fragment-ordered operands for the W2 GEMM
// A (activations): [((ks*64 + mtile)*2 + hl)*128 + lane*4 + slot], 262144 u32
__device__ unsigned g_aF[262144];
// B (W2):          [((ks*264 + ntile)*2 + hl)*64 + lane*2 + slot], 540672 u32
__device__ unsigned g_w2F[540672];

// per-batch-group LSTM sync counters (32 per layer)
__device__ unsigned g_grpCnt[64];

__global__ void zero_cnt() {
    if (threadIdx.x < 64) g_grpCnt[threadIdx.x] = 0u;
}

// ----------------------------------------------------------------------------
// tf32 helpers (portable PTX — ptxas here targets plain sm_103, no tcgen05)
// ----------------------------------------------------------------------------
__device__ __forceinline__ unsigned f2tf32(float v) {
    unsigned r;
    asm("cvt.rna.tf32.f32 %0, %1;" : "=r"(r) : "f"(v));
    return r;
}
__device__ __forceinline__ void mma_tf32(float c[4], uint4 a, uint2 b) {
    asm volatile(
        "mma.sync.aligned.m16n8k8.row.col.f32.tf32.tf32.f32 "
        "{%0,%1,%2,%3}, {%4,%5,%6,%7}, {%8,%9}, {%0,%1,%2,%3};"
        : "+f"(c[0]), "+f"(c[1]), "+f"(c[2]), "+f"(c[3])
        : "r"(a.x), "r"(a.y), "r"(a.z), "r"(a.w), "r"(b.x), "r"(b.y));
}

// ----------------------------------------------------------------------------
// One-time W2 -> tf32 hi/lo fragment-order conversion (per launch).
// ----------------------------------------------------------------------------
__global__ void __launch_bounds__(256)
w2_frag(const float* __restrict__ W2)
{
    int e = blockIdx.x * 256 + threadIdx.x;
    if (e >= W2_ROWS * 128) return;
    int n = e >> 7, k = e & 127;
    float v = W2[e];
    unsigned hb = f2tf32(v);
    unsigned lb = f2tf32(v - __uint_as_float(hb));
    int ks = k >> 3, k8 = k & 7, nt = n >> 3;
    int lane = (n & 7) * 4 + (k8 & 3);
    int slot = k8 >> 2;
    int idx = ((ks * 264 + nt) * 2) * 64 + lane * 2 + slot;
    g_w2F[idx] = hb;
    g_w2F[idx + 64] = lb;
}

// ----------------------------------------------------------------------------
// W2 GEMM via 3xTF32 mma.sync, operands pre-fragmented in global.
// CTA tile 128x64 (grid 8x33), 256 thr, 8 warps (4m x 2n), K chunked by 32.
// Staging = straight LDG.128 -> STS.128 copies (no cvt, no scatter).
// ----------------------------------------------------------------------------
__global__ void __launch_bounds__(256)
gemm_w2_tc(const float* __restrict__ b2, float* __restrict__ Fout)
{
    extern __shared__ unsigned pool[];          // 12288 u32 = 48KB
    unsigned* As = pool;                        // 8192 u32
    unsigned* Bs = pool + 8192;                 // 4096 u32
    const int tid = threadIdx.x;
    const int w = tid >> 5, l = tid & 31;
    const int wm = w & 3, wn = w >> 2;
    const int bx = blockIdx.x, by = blockIdx.y;
    const int m0 = bx * 128, n0 = by * 64;

    float acc[2][4][4];
#pragma unroll
    for (int mt = 0; mt < 2; mt++)
#pragma unroll
        for (int nt = 0; nt < 4; nt++)
#pragma unroll
            for (int i = 0; i < 4; i++) acc[mt][nt][i] = 0.f;

    const uint4* srcA = (const uint4*)g_aF;
    const uint4* srcB = (const uint4*)g_w2F;

    for (int c = 0; c < 4; c++) {
        if (c) __syncthreads();
        // A chunk: 2048 uint4. smem block = (ksl*8+mtl)*2+hl, 32 uint4 each.
#pragma unroll
        for (int q = 0; q < 8; q++) {
            int e4 = tid + q * 256;
            int blk = e4 >> 5, w32 = e4 & 31;
            int ksl = blk >> 4, rest = blk & 15;        // mtl = rest>>1, hl = rest&1
            int gblk = (((c * 4 + ksl) * 64) + bx * 8 + (rest >> 1)) * 2 + (rest & 1);
            ((uint4*)As)[e4] = srcA[gblk * 32 + w32];
        }
        // B chunk: 1024 uint4. smem block = (ksl*8+ntl)*2+hl, 16 uint4 each.
#pragma unroll
        for (int q = 0; q < 4; q++) {
            int e4 = tid + q * 256;
            int blk = e4 >> 4, w16 = e4 & 15;
            int ksl = blk >> 4, rest = blk & 15;
            int gblk = ((c * 4 + ksl) * 264 + by * 8 + (rest >> 1)) * 2 + (rest & 1);
            ((uint4*)Bs)[e4] = srcB[gblk * 16 + w16];
        }
        __syncthreads();

#pragma unroll
        for (int kstep = 0; kstep < 4; kstep++) {
            uint4 Ahi[2], Alo[2];
            uint2 Bhi[4], Blo[4];
#pragma unroll
            for (int mt = 0; mt < 2; mt++) {
                int mtile = wm * 2 + mt;
                int base = ((kstep * 8 + mtile) * 2) * 128 + l * 4;
                Ahi[mt] = *(const uint4*)&As[base];
                Alo[mt] = *(const uint4*)&As[base + 128];
            }
#pragma unroll
            for (int nt = 0; nt < 4; nt++) {
                int ntile = wn * 4 + nt;
                int base = ((kstep * 8 + ntile) * 2) * 64 + l * 2;
                Bhi[nt] = *(const uint2*)&Bs[base];
                Blo[nt] = *(const uint2*)&Bs[base + 64];
            }
#pragma unroll
            for (int mt = 0; mt < 2; mt++)
#pragma unroll
                for (int nt = 0; nt < 4; nt++) {
                    mma_tf32(acc[mt][nt], Ahi[mt], Bhi[nt]);
                    mma_tf32(acc[mt][nt], Ahi[mt], Blo[nt]);
                    mma_tf32(acc[mt][nt], Alo[mt], Bhi[nt]);
                }
        }
    }

    // epilogue: fragments -> padded smem -> coalesced float4 stores
    __syncthreads();
    float* S = (float*)pool;                    // 128 x 68 floats
    const int g = l >> 2, tq = l & 3;
#pragma unroll
    for (int mt = 0; mt < 2; mt++)
#pragma unroll
        for (int nt = 0; nt < 4; nt++) {
            int row = wm * 32 + mt * 16 + g;
            int col = wn * 32 + nt * 8 + tq * 2;
            S[row * 68 + col]           = acc[mt][nt][0];
            S[row * 68 + col + 1]       = acc[mt][nt][1];
            S[(row + 8) * 68 + col]     = acc[mt][nt][2];
            S[(row + 8) * 68 + col + 1] = acc[mt][nt][3];
        }
    __syncthreads();
#pragma unroll
    for (int q = 0; q < 8; q++) {
        int e = tid + q * 256;
        int r = e >> 4, c4 = (e & 15) * 4;
        float4 v = *(const float4*)&S[r * 68 + c4];
        float4 o;
        o.x = tanhf(v.x + b2[n0 + c4 + 0]);
        o.y = tanhf(v.y + b2[n0 + c4 + 1]);
        o.z = tanhf(v.z + b2[n0 + c4 + 2]);
        o.w = tanhf(v.w + b2[n0 + c4 + 3]);
        *(float4*)&Fout[(size_t)(m0 + r) * W2_ROWS + n0 + c4] = o;
    }
}

// ----------------------------------------------------------------------------
// Generic C = act(A @ B^T + bias). Scalar FFMA.
// ----------------------------------------------------------------------------
template<int ACT>
__global__ void __launch_bounds__(256)
gemm_tn(const float* __restrict__ A, const float* __restrict__ Bm,
        const float* __restrict__ bias, float* __restrict__ C,
        int M, int N, int K)
{
    __shared__ __align__(16) float As[16][64];
    __shared__ __align__(16) float Bs[16][64];
    const int m0 = blockIdx.x * 64;
    const int n0 = blockIdx.y * 64;
    const int tid = threadIdx.x;
    const int tr = tid >> 4;
    const int tc = tid & 15;

    float acc[4][4];
#pragma unroll
    for (int i = 0; i < 4; i++)
#pragma unroll
        for (int j = 0; j < 4; j++) acc[i][j] = 0.f;

    const int ml = tid >> 2;
    const int kq = (tid & 3) * 4;

    for (int k0 = 0; k0 < K; k0 += 16) {
        {
            float4 v = *(const float4*)(A + (size_t)(m0 + ml) * K + k0 + kq);
            As[kq+0][ml] = v.x; As[kq+1][ml] = v.y; As[kq+2][ml] = v.z; As[kq+3][ml] = v.w;
            float4 w = make_float4(0.f, 0.f, 0.f, 0.f);
            if (n0 + ml < N)
                w = *(const float4*)(Bm + (size_t)(n0 + ml) * K + k0 + kq);
            Bs[kq+0][ml] = w.x; Bs[kq+1][ml] = w.y; Bs[kq+2][ml] = w.z; Bs[kq+3][ml] = w.w;
        }
        __syncthreads();
#pragma unroll
        for (int kk = 0; kk < 16; kk++) {
            float4 a4 = *(const float4*)&As[kk][tr*4];
            float4 b4 = *(const float4*)&Bs[kk][tc*4];
            float av[4] = {a4.x, a4.y, a4.z, a4.w};
            float bv[4] = {b4.x, b4.y, b4.z, b4.w};
#pragma unroll
            for (int i = 0; i < 4; i++)
#pragma unroll
                for (int j = 0; j < 4; j++) acc[i][j] += av[i] * bv[j];
        }
        __syncthreads();
    }

#pragma unroll
    for (int j = 0; j < 4; j++) {
        int n = n0 + tc*4 + j;
        if (n >= N) continue;
        float bb = bias ? bias[n] : 0.f;
#pragma unroll
        for (int i = 0; i < 4; i++) {
            float v = acc[i][j] + bb;
            if (ACT == 1) v = tanhf(v);
            else if (ACT == 2) v = fmaxf(v, 0.f);
            C[(size_t)(m0 + tr*4 + i) * N + n] = v;
        }
    }
}

// ----------------------------------------------------------------------------
// Persistent LSTM layer: 128 CTAs = 32 batch-groups x 4 h-tiles, 512 threads.
// Sync is PER-GROUP (4 CTAs share a batch group) via monotonic counters —
// no global barrier. xw[t] prefetched into registers at step top so the DRAM
// latency hides under the recurrent GEMM.
// ----------------------------------------------------------------------------
__global__ void __launch_bounds__(512)
lstm_persist(const float* __restrict__ xw,
             const float* __restrict__ Whh,
             const float* __restrict__ bih, const float* __restrict__ bhh,
             float* __restrict__ h_buf, int h_sb, int mode, int nsteps, int cbase)
{
    extern __shared__ __align__(16) float Wsm[];
    __shared__ __align__(16) float As[ENC_H][33];
    __shared__ float Gs[32][132];
    __shared__ float bsum[128];

    const int grp = blockIdx.x & 31;
    const int b0 = grp * 32;
    const int h0 = (blockIdx.x >> 5) * 32;
    const int tid = threadIdx.x;
    const int tr = tid >> 5;
    const int tc = tid & 31;

#pragma unroll
    for (int q = 0; q < 8; q++) {
        int e = tid + q * 512;
        int c = e & 127, kq = (e >> 7) * 4;
        int jg = (c >> 5) * ENC_H + h0 + (c & 31);
        float4 v = *(const float4*)(Whh + (size_t)jg * ENC_H + kq);
        Wsm[(kq+0)*128 + c] = v.x; Wsm[(kq+1)*128 + c] = v.y;
        Wsm[(kq+2)*128 + c] = v.z; Wsm[(kq+3)*128 + c] = v.w;
    }
    if (tid < 128) {
        int jg = (tid >> 5) * ENC_H + h0 + (tid & 31);
        bsum[tid] = bih[jg] + bhh[jg];
    }
    float creg[2] = {0.f, 0.f};
    __syncthreads();

    for (int t = 0; t < nsteps; t++) {
        // prefetch this step's xw slice into registers (independent of h)
        float xr[2][4];
#pragma unroll
        for (int j = 0; j < 4; j++) {
            int c = tc*4 + j;
            int jg = (c >> 5) * ENC_H + h0 + (c & 31);
#pragma unroll
            for (int p = 0; p < 2; p++)
                xr[p][j] = xw[(size_t)(b0 + 2*tr + p) * (T_HIST*G4)
                              + (size_t)t * G4 + jg];
        }

        float acc[2][4];
#pragma unroll
        for (int p = 0; p < 2; p++)
#pragma unroll
            for (int j = 0; j < 4; j++) acc[p][j] = 0.f;

        if (t > 0) {
            // wait for all 4 CTAs of this batch group to finish step t-1
            if (tid == 0) {
                while (__ldcg(&g_grpCnt[cbase + grp]) < 4u * (unsigned)t)
                    __nanosleep(20);
            }
            __syncthreads();
            const float* hp = h_buf + (mode ? (size_t)((t-1) & 1) * BB * ENC_H
                                            : (size_t)(t-1) * ENC_H);
#pragma unroll
            for (int q = 0; q < 2; q++) {
                int e = tid + q * 512;
                int m = e & 31, kq = (e >> 5) * 4;
                float4 v = __ldcg((const float4*)(hp + (size_t)(b0 + m) * h_sb + kq));
                As[kq+0][m] = v.x; As[kq+1][m] = v.y; As[kq+2][m] = v.z; As[kq+3][m] = v.w;
            }
            __syncthreads();
#pragma unroll 8
            for (int kk = 0; kk < ENC_H; kk++) {
                float a0 = As[kk][2*tr];
                float a1 = As[kk][2*tr + 1];
                float4 w = *(const float4*)&Wsm[kk*128 + tc*4];
                acc[0][0] += a0 * w.x; acc[0][1] += a0 * w.y;
                acc[0][2] += a0 * w.z; acc[0][3] += a0 * w.w;
                acc[1][0] += a1 * w.x; acc[1][1] += a1 * w.y;
                acc[1][2] += a1 * w.z; acc[1][3] += a1 * w.w;
            }
        }

#pragma unroll
        for (int j = 0; j < 4; j++) {
            int c = tc*4 + j;
            float bb = bsum[c];
#pragma unroll
            for (int p = 0; p < 2; p++) {
                int r = 2*tr + p;
                Gs[r][c] = acc[p][j] + xr[p][j] + bb;
            }
        }
        __syncthreads();

        float* ho = h_buf + (mode ? (size_t)(t & 1) * BB * ENC_H : (size_t)t * ENC_H);
#pragma unroll
        for (int q = 0; q < 2; q++) {
            int e = tid + q * 512;
            int r = e >> 5, hh = e & 31;
            float gi = Gs[r][hh];
            float gf = Gs[r][32 + hh];
            float gg = Gs[r][64 + hh];
            float go = Gs[r][96 + hh];
            float si = 1.f / (1.f + expf(-gi));
            float sf = 1.f / (1.f + expf(-gf));
            float so = 1.f / (1.f + expf(-go));
            float tg = tanhf(gg);
            float cn = sf * creg[q] + si * tg;
            creg[q] = cn;
            float hn = so * tanhf(cn);
            ho[(size_t)(b0 + r) * h_sb + h0 + hh] = hn;
        }
        __syncthreads();
        if (tid == 0) {
            __threadfence();
            atomicAdd(&g_grpCnt[cbase + grp], 1u);
        }
    }
}

// ----------------------------------------------------------------------------
// CDE stage prep: zs = z + sum a_j k_j; LayerNorm; a = relu(zn@W1^T + b1),
// written directly as tf32 hi/lo fragments into g_aF. grid = B/32, 256 thr.
// ----------------------------------------------------------------------------
__global__ void __launch_bounds__(256)
cde_prep(const float* __restrict__ gamma, const float* __restrict__ beta,
         const float* __restrict__ W1, const float* __restrict__ b1,
         float a0, float a1, float a2, float a3, float a4, int nk)
{
    __shared__ __align__(16) float znT[64][36];
    __shared__ __align__(16) float pool[8192];
    __shared__ float mu[32], rstd[32];
    const int b0 = blockIdx.x * 32;
    const int tid = threadIdx.x;
    const float av[5] = {a0, a1, a2, a3, a4};
    float* zs = pool;

#pragma unroll
    for (int q = 0; q < 8; q++) {
        int e = tid + q * 256;
        int r = e >> 6, k = e & 63;
        size_t gi = (size_t)(b0 + r) * CDE_H + k;
        float v = g_z[gi];
        for (int j = 0; j < nk; j++) v += av[j] * g_k[j][gi];
        zs[r * 65 + k] = v;
    }
    __syncthreads();
    {
        int row = tid >> 3, lane = tid & 7;
        float s = 0.f;
        for (int k = lane; k < 64; k += 8) s += zs[row * 65 + k];
#pragma unroll
        for (int d = 1; d < 8; d <<= 1) s += __shfl_xor_sync(0xffffffffu, s, d, 8);
        float m = s * (1.f / 64.f);
        float q2 = 0.f;
        for (int k = lane; k < 64; k += 8) { float dd = zs[row * 65 + k] - m; q2 += dd * dd; }
#pragma unroll
        for (int d = 1; d < 8; d <<= 1) q2 += __shfl_xor_sync(0xffffffffu, q2, d, 8);
        if (lane == 0) { mu[row] = m; rstd[row] = rsqrtf(q2 * (1.f / 64.f) + 1e-5f); }
    }
    __syncthreads();
#pragma unroll
    for (int q = 0; q < 8; q++) {
        int e = tid + q * 256;
        int k = e >> 5, r = e & 31;
        znT[k][r] = (zs[r * 65 + k] - mu[r]) * rstd[r] * gamma[k] + beta[k];
    }
    __syncthreads();

    float* W1s = pool;
#pragma unroll
    for (int q = 0; q < 32; q++) {
        int e = tid + q * 256;
        int j = e >> 6, k = e & 63;
        W1s[k * 128 + j] = W1[e];
    }
    __syncthreads();

    const int tr = tid >> 5;
    const int tc = tid & 31;
    float acc[4][4];
#pragma unroll
    for (int i = 0; i < 4; i++)
#pragma unroll
        for (int j = 0; j < 4; j++) acc[i][j] = 0.f;
#pragma unroll 4
    for (int k = 0; k < 64; k++) {
        float zf[4];
#pragma unroll
        for (int i = 0; i < 4; i++) zf[i] = znT[k][tr*4 + i];
        float4 w4 = *(const float4*)&W1s[k * 128 + tc*4];
        float wv[4] = {w4.x, w4.y, w4.z, w4.w};
#pragma unroll
        for (int i = 0; i < 4; i++)
#pragma unroll
            for (int j = 0; j < 4; j++) acc[i][j] += zf[i] * wv[j];
    }
    // write relu(acc+b1) as tf32 hi/lo fragments
#pragma unroll
    for (int j = 0; j < 4; j++) {
        int col = tc*4 + j;
        float bb = b1[col];
        int ks = col >> 3, k8 = col & 7;
#pragma unroll
        for (int i = 0; i < 4; i++) {
            int r = b0 + tr*4 + i;
            float v = fmaxf(acc[i][j] + bb, 0.f);
            unsigned hb = f2tf32(v);
            unsigned lb = f2tf32(v - __uint_as_float(hb));
            int mt = r >> 4, r16 = r & 15;
            int lane = (r16 & 7) * 4 + (k8 & 3);
            int slot = ((r16 >> 3) & 1) | ((k8 >> 2) << 1);
            int idx = ((ks * 64 + mt) * 2) * 128 + lane * 4 + slot;
            g_aF[idx] = hb;
            g_aF[idx + 128] = lb;
        }
    }
}

// ----------------------------------------------------------------------------
// Contract: k_s = sum_ch f * dX; stage 6 applies DP45 z-update.
// grid = B blocks, 64 threads.
// ----------------------------------------------------------------------------
__global__ void __launch_bounds__(64)
cde_contract(const float* __restrict__ coeffs, int sidx, int idx, float u,
             int do_update, float c1, float c3, float c4, float c5, float c6)
{
    __shared__ float dX[CHN];
    const int b = blockIdx.x;
    const int tid = threadIdx.x;
    if (tid < CHN) {
        size_t base = ((size_t)b * 4 + idx) * 4 * CHN;
        float A1 = coeffs[base + 1 * CHN + tid];
        float A2 = coeffs[base + 2 * CHN + tid];
        float A3 = coeffs[base + 3 * CHN + tid];
        dX[tid] = A1 + 2.f * A2 * u + 3.f * A3 * u * u;
    }
    __syncthreads();
    const float* fr = g_f + (size_t)b * W2_ROWS + tid * CHN;
    float acc = 0.f;
#pragma unroll
    for (int ch = 0; ch < CHN; ch++) acc += fr[ch] * dX[ch];
    size_t gi = (size_t)b * CDE_H + tid;
    g_k[sidx][gi] = acc;
    if (do_update) {
        g_z[gi] += c1 * g_k[0][gi] + c3 * g_k[2][gi] + c4 * g_k[3][gi]
                 + c5 * g_k[4][gi] + c6 * acc;
    }
}

// ----------------------------------------------------------------------------
// Host orchestration
// ----------------------------------------------------------------------------
extern "C" void kernel_launch(void* const* d_in, const int* in_sizes, int n_in,
                              void* d_out, int out_size)
{
    const float* hist   = (const float*)d_in[0];
    const float* coeffs = (const float*)d_in[1];
    const float* W_ih0 = (const float*)d_in[3];
    const float* W_hh0 = (const float*)d_in[4];
    const float* b_ih0 = (const float*)d_in[5];
    const float* b_hh0 = (const float*)d_in[6];
    const float* W_ih1 = (const float*)d_in[7];
    const float* W_hh1 = (const float*)d_in[8];
    const float* b_ih1 = (const float*)d_in[9];
    const float* b_hh1 = (const float*)d_in[10];
    const float* W_map = (const float*)d_in[11];
    const float* b_map = (const float*)d_in[12];
    const float* gamma = (const float*)d_in[13];
    const float* beta  = (const float*)d_in[14];
    const float* W1    = (const float*)d_in[15];
    const float* b1    = (const float*)d_in[16];
    const float* W2    = (const float*)d_in[17];
    const float* b2    = (const float*)d_in[18];
    const float* W_pred = (const float*)d_in[19];
    const float* b_pred = (const float*)d_in[20];
    float* out = (float*)d_out;

    float *p_xW, *p_seq0, *p_h1, *p_z, *p_f;
    cudaGetSymbolAddress((void**)&p_xW,   g_xW);
    cudaGetSymbolAddress((void**)&p_seq0, g_seq0);
    cudaGetSymbolAddress((void**)&p_h1,   g_h1);
    cudaGetSymbolAddress((void**)&p_z,    g_z);
    cudaGetSymbolAddress((void**)&p_f,    g_f);

    const int WSM_BYTES = 128 * 128 * 4;
    const int TC_SMEM = 12288 * 4;
    cudaFuncSetAttribute(lstm_persist, cudaFuncAttributeMaxDynamicSharedMemorySize, WSM_BYTES);
    cudaFuncSetAttribute(gemm_w2_tc, cudaFuncAttributeMaxDynamicSharedMemorySize, TC_SMEM);

    zero_cnt<<<1, 64>>>();
    w2_frag<<<(W2_ROWS*128 + 255)/256, 256>>>(W2);

    // ---------------- LSTM layer 0 ----------------
    gemm_tn<0><<<dim3(BB*T_HIST/64, G4/64), 256>>>(hist, W_ih0, nullptr, p_xW,
                                                   BB*T_HIST, G4, ENC_IN);
    lstm_persist<<<128, 512, WSM_BYTES>>>(p_xW, W_hh0, b_ih0, b_hh0,
                                          p_seq0, T_HIST*ENC_H, 0, T_HIST, 0);

    // ---------------- LSTM layer 1 ----------------
    gemm_tn<0><<<dim3(BB*T_HIST/64, G4/64), 256>>>(p_seq0, W_ih1, nullptr, p_xW,
                                                   BB*T_HIST, G4, ENC_H);
    lstm_persist<<<128, 512, WSM_BYTES>>>(p_xW, W_hh1, b_ih1, b_hh1,
                                          p_h1, ENC_H, 1, T_HIST, 32);
    const float* context = p_h1 + (size_t)((T_HIST - 1) & 1) * BB * ENC_H;

    // ---------------- map to z0 ----------------
    gemm_tn<1><<<dim3(BB/64, 1), 256>>>(context, W_map, b_map, p_z, BB, CDE_H, ENC_H);

    // ---------------- Neural CDE, RK45 (Dormand-Prince) ----------------
    const double dt = 1.0 / N_STEPS;
    const double ACF[6][5] = {
        {0, 0, 0, 0, 0},
        {1.0/5, 0, 0, 0, 0},
        {3.0/40, 9.0/40, 0, 0, 0},
        {44.0/45, -56.0/15, 32.0/9, 0, 0},
        {19372.0/6561, -25360.0/2187, 64448.0/6561, -212.0/729, 0},
        {9017.0/3168, -355.0/33, 46732.0/5247, 49.0/176, -5103.0/18656}
    };
    const double COFF[6] = {0.0, 1.0/5, 3.0/10, 4.0/5, 8.0/9, 1.0};
    const double BU[5] = {35.0/384, 500.0/1113, 125.0/192, -2187.0/6784, 11.0/84};

    for (int i = 0; i < N_STEPS; i++) {
        float t = (float)(i * dt);
        for (int s = 0; s < 6; s++) {
            cde_prep<<<BB/32, 256>>>(gamma, beta, W1, b1,
                (float)(dt*ACF[s][0]), (float)(dt*ACF[s][1]), (float)(dt*ACF[s][2]),
                (float)(dt*ACF[s][3]), (float)(dt*ACF[s][4]), s);

            gemm_w2_tc<<<dim3(BB/128, W2_ROWS/64), 256, TC_SMEM>>>(b2, p_f);

            float ts = t + (float)(dt * COFF[s]);
            int idx = (int)floorf(ts / 0.25f);
            if (idx < 0) idx = 0;
            if (idx > 3) idx = 3;
            float u = ts - (float)idx * 0.25f;
            cde_contract<<<BB, CDE_H>>>(coeffs, s, idx, u, (s == 5) ? 1 : 0,
                (float)(dt*BU[0]), (float)(dt*BU[1]), (float)(dt*BU[2]),
                (float)(dt*BU[3]), (float)(dt*BU[4]));
        }
    }

    // ---------------- final projection ----------------
    gemm_tn<0><<<dim3(BB/64, (NZ + 63)/64), 256>>>(p_z, W_pred, b_pred, out,
                                                   BB, NZ, CDE_H);
}

// round 12
// speedup vs baseline: 2.4993x; 1.0498x over previous
#include <cuda_runtime.h>
#include <cuda_bf16.h>

#define BB 1024
#define T_HIST 50
#define ENC_IN 96
#define ENC_H 128
#define G4 (4*ENC_H)          // 512
#define CDE_H 64
#define CHN 33
#define NZ 10000
#define MLP_H 128
#define W2_ROWS (CHN*CDE_H)   // 2112
#define N_STEPS 16

// ----------------------------------------------------------------------------
// Scratch (static device globals — no allocation)
// ----------------------------------------------------------------------------
__device__ float g_xW[BB*T_HIST*G4];
__device__ float g_seq0[BB*T_HIST*ENC_H];
__device__ float g_h1[2][BB*ENC_H];
__device__ float g_z[BB*CDE_H];
__device__ float g_k[6][BB*CDE_H];
__device__ float g_f[BB*W2_ROWS];

// tf32 fragment-ordered operands for the W2 GEMM
__device__ unsigned g_aF[262144];
__device__ unsigned g_w2F[540672];

// per-batch-group LSTM sync counters (32 per layer)
__device__ unsigned g_grpCnt[64];

__global__ void zero_cnt() {
    if (threadIdx.x < 64) g_grpCnt[threadIdx.x] = 0u;
}

// ----------------------------------------------------------------------------
// tf32 helpers (portable PTX — ptxas here targets plain sm_103, no tcgen05)
// ----------------------------------------------------------------------------
__device__ __forceinline__ unsigned f2tf32(float v) {
    unsigned r;
    asm("cvt.rna.tf32.f32 %0, %1;" : "=r"(r) : "f"(v));
    return r;
}
__device__ __forceinline__ void mma_tf32(float c[4], uint4 a, uint2 b) {
    asm volatile(
        "mma.sync.aligned.m16n8k8.row.col.f32.tf32.tf32.f32 "
        "{%0,%1,%2,%3}, {%4,%5,%6,%7}, {%8,%9}, {%0,%1,%2,%3};"
        : "+f"(c[0]), "+f"(c[1]), "+f"(c[2]), "+f"(c[3])
        : "r"(a.x), "r"(a.y), "r"(a.z), "r"(a.w), "r"(b.x), "r"(b.y));
}

// ----------------------------------------------------------------------------
// One-time W2 -> tf32 hi/lo fragment-order conversion (per launch).
// ----------------------------------------------------------------------------
__global__ void __launch_bounds__(256)
w2_frag(const float* __restrict__ W2)
{
    int e = blockIdx.x * 256 + threadIdx.x;
    if (e >= W2_ROWS * 128) return;
    int n = e >> 7, k = e & 127;
    float v = W2[e];
    unsigned hb = f2tf32(v);
    unsigned lb = f2tf32(v - __uint_as_float(hb));
    int ks = k >> 3, k8 = k & 7, nt = n >> 3;
    int lane = (n & 7) * 4 + (k8 & 3);
    int slot = k8 >> 2;
    int idx = ((ks * 264 + nt) * 2) * 64 + lane * 2 + slot;
    g_w2F[idx] = hb;
    g_w2F[idx + 64] = lb;
}

// ----------------------------------------------------------------------------
// W2 GEMM via 3xTF32 mma.sync, operands pre-fragmented in global. (round-11)
// ----------------------------------------------------------------------------
__global__ void __launch_bounds__(256)
gemm_w2_tc(const float* __restrict__ b2, float* __restrict__ Fout)
{
    extern __shared__ unsigned pool[];          // 12288 u32 = 48KB
    unsigned* As = pool;
    unsigned* Bs = pool + 8192;
    const int tid = threadIdx.x;
    const int w = tid >> 5, l = tid & 31;
    const int wm = w & 3, wn = w >> 2;
    const int bx = blockIdx.x, by = blockIdx.y;
    const int m0 = bx * 128, n0 = by * 64;

    float acc[2][4][4];
#pragma unroll
    for (int mt = 0; mt < 2; mt++)
#pragma unroll
        for (int nt = 0; nt < 4; nt++)
#pragma unroll
            for (int i = 0; i < 4; i++) acc[mt][nt][i] = 0.f;

    const uint4* srcA = (const uint4*)g_aF;
    const uint4* srcB = (const uint4*)g_w2F;

    for (int c = 0; c < 4; c++) {
        if (c) __syncthreads();
#pragma unroll
        for (int q = 0; q < 8; q++) {
            int e4 = tid + q * 256;
            int blk = e4 >> 5, w32 = e4 & 31;
            int ksl = blk >> 4, rest = blk & 15;
            int gblk = (((c * 4 + ksl) * 64) + bx * 8 + (rest >> 1)) * 2 + (rest & 1);
            ((uint4*)As)[e4] = srcA[gblk * 32 + w32];
        }
#pragma unroll
        for (int q = 0; q < 4; q++) {
            int e4 = tid + q * 256;
            int blk = e4 >> 4, w16 = e4 & 15;
            int ksl = blk >> 4, rest = blk & 15;
            int gblk = ((c * 4 + ksl) * 264 + by * 8 + (rest >> 1)) * 2 + (rest & 1);
            ((uint4*)Bs)[e4] = srcB[gblk * 16 + w16];
        }
        __syncthreads();

#pragma unroll
        for (int kstep = 0; kstep < 4; kstep++) {
            uint4 Ahi[2], Alo[2];
            uint2 Bhi[4], Blo[4];
#pragma unroll
            for (int mt = 0; mt < 2; mt++) {
                int mtile = wm * 2 + mt;
                int base = ((kstep * 8 + mtile) * 2) * 128 + l * 4;
                Ahi[mt] = *(const uint4*)&As[base];
                Alo[mt] = *(const uint4*)&As[base + 128];
            }
#pragma unroll
            for (int nt = 0; nt < 4; nt++) {
                int ntile = wn * 4 + nt;
                int base = ((kstep * 8 + ntile) * 2) * 64 + l * 2;
                Bhi[nt] = *(const uint2*)&Bs[base];
                Blo[nt] = *(const uint2*)&Bs[base + 64];
            }
#pragma unroll
            for (int mt = 0; mt < 2; mt++)
#pragma unroll
                for (int nt = 0; nt < 4; nt++) {
                    mma_tf32(acc[mt][nt], Ahi[mt], Bhi[nt]);
                    mma_tf32(acc[mt][nt], Ahi[mt], Blo[nt]);
                    mma_tf32(acc[mt][nt], Alo[mt], Bhi[nt]);
                }
        }
    }

    __syncthreads();
    float* S = (float*)pool;
    const int g = l >> 2, tq = l & 3;
#pragma unroll
    for (int mt = 0; mt < 2; mt++)
#pragma unroll
        for (int nt = 0; nt < 4; nt++) {
            int row = wm * 32 + mt * 16 + g;
            int col = wn * 32 + nt * 8 + tq * 2;
            S[row * 68 + col]           = acc[mt][nt][0];
            S[row * 68 + col + 1]       = acc[mt][nt][1];
            S[(row + 8) * 68 + col]     = acc[mt][nt][2];
            S[(row + 8) * 68 + col + 1] = acc[mt][nt][3];
        }
    __syncthreads();
#pragma unroll
    for (int q = 0; q < 8; q++) {
        int e = tid + q * 256;
        int r = e >> 4, c4 = (e & 15) * 4;
        float4 v = *(const float4*)&S[r * 68 + c4];
        float4 o;
        o.x = tanhf(v.x + b2[n0 + c4 + 0]);
        o.y = tanhf(v.y + b2[n0 + c4 + 1]);
        o.z = tanhf(v.z + b2[n0 + c4 + 2]);
        o.w = tanhf(v.w + b2[n0 + c4 + 3]);
        *(float4*)&Fout[(size_t)(m0 + r) * W2_ROWS + n0 + c4] = o;
    }
}

// ----------------------------------------------------------------------------
// Generalized 3xTF32 GEMM: C = A @ B^T (+bias). A [M,K], B [N,K] f32 row-major.
// On-the-fly cvt staging (round-10 verified logic). M%128==0, N%64==0, K%32==0.
// ----------------------------------------------------------------------------
__global__ void __launch_bounds__(256)
gemm_tf32(const float* __restrict__ A, const float* __restrict__ Bm,
          const float* __restrict__ bias, float* __restrict__ C,
          int M, int N, int K)
{
    extern __shared__ unsigned pool[];          // 12288 u32 = 48KB
    unsigned* As = pool;
    unsigned* Bs = pool + 8192;
    const int tid = threadIdx.x;
    const int w = tid >> 5, l = tid & 31;
    const int wm = w & 3, wn = w >> 2;
    const int m0 = blockIdx.x * 128, n0 = blockIdx.y * 64;
    const int KC = K >> 5;

    float acc[2][4][4];
#pragma unroll
    for (int mt = 0; mt < 2; mt++)
#pragma unroll
        for (int nt = 0; nt < 4; nt++)
#pragma unroll
            for (int i = 0; i < 4; i++) acc[mt][nt][i] = 0.f;

    for (int c = 0; c < KC; c++) {
        const int k0 = c * 32;
        if (c) __syncthreads();
#pragma unroll
        for (int q = 0; q < 16; q++) {
            int e = tid + q * 256;
            int r = e >> 5, kk = e & 31;
            float v = A[(size_t)(m0 + r) * K + k0 + kk];
            unsigned hb = f2tf32(v);
            unsigned lb = f2tf32(v - __uint_as_float(hb));
            int kstep = kk >> 3, k8 = kk & 7;
            int mtile = r >> 4, r16 = r & 15;
            int lane = (r16 & 7) * 4 + (k8 & 3);
            int slot = ((r16 >> 3) & 1) | ((k8 >> 2) << 1);
            int base = ((kstep * 8 + mtile) * 2) * 128 + lane * 4 + slot;
            As[base] = hb;
            As[base + 128] = lb;
        }
#pragma unroll
        for (int q = 0; q < 8; q++) {
            int e = tid + q * 256;
            int n = e >> 5, kk = e & 31;
            float v = Bm[(size_t)(n0 + n) * K + k0 + kk];
            unsigned hb = f2tf32(v);
            unsigned lb = f2tf32(v - __uint_as_float(hb));
            int kstep = kk >> 3, k8 = kk & 7;
            int ntile = n >> 3;
            int lane = (n & 7) * 4 + (k8 & 3);
            int slot = (k8 >> 2) & 1;
            int base = ((kstep * 8 + ntile) * 2) * 64 + lane * 2 + slot;
            Bs[base] = hb;
            Bs[base + 64] = lb;
        }
        __syncthreads();

#pragma unroll
        for (int kstep = 0; kstep < 4; kstep++) {
            uint4 Ahi[2], Alo[2];
            uint2 Bhi[4], Blo[4];
#pragma unroll
            for (int mt = 0; mt < 2; mt++) {
                int mtile = wm * 2 + mt;
                int base = ((kstep * 8 + mtile) * 2) * 128 + l * 4;
                Ahi[mt] = *(const uint4*)&As[base];
                Alo[mt] = *(const uint4*)&As[base + 128];
            }
#pragma unroll
            for (int nt = 0; nt < 4; nt++) {
                int ntile = wn * 4 + nt;
                int base = ((kstep * 8 + ntile) * 2) * 64 + l * 2;
                Bhi[nt] = *(const uint2*)&Bs[base];
                Blo[nt] = *(const uint2*)&Bs[base + 64];
            }
#pragma unroll
            for (int mt = 0; mt < 2; mt++)
#pragma unroll
                for (int nt = 0; nt < 4; nt++) {
                    mma_tf32(acc[mt][nt], Ahi[mt], Bhi[nt]);
                    mma_tf32(acc[mt][nt], Ahi[mt], Blo[nt]);
                    mma_tf32(acc[mt][nt], Alo[mt], Bhi[nt]);
                }
        }
    }

    __syncthreads();
    float* S = (float*)pool;
    const int g = l >> 2, tq = l & 3;
#pragma unroll
    for (int mt = 0; mt < 2; mt++)
#pragma unroll
        for (int nt = 0; nt < 4; nt++) {
            int row = wm * 32 + mt * 16 + g;
            int col = wn * 32 + nt * 8 + tq * 2;
            S[row * 68 + col]           = acc[mt][nt][0];
            S[row * 68 + col + 1]       = acc[mt][nt][1];
            S[(row + 8) * 68 + col]     = acc[mt][nt][2];
            S[(row + 8) * 68 + col + 1] = acc[mt][nt][3];
        }
    __syncthreads();
#pragma unroll
    for (int q = 0; q < 8; q++) {
        int e = tid + q * 256;
        int r = e >> 4, c4 = (e & 15) * 4;
        float4 v = *(const float4*)&S[r * 68 + c4];
        if (bias) {
            v.x += bias[n0 + c4 + 0];
            v.y += bias[n0 + c4 + 1];
            v.z += bias[n0 + c4 + 2];
            v.w += bias[n0 + c4 + 3];
        }
        *(float4*)&C[(size_t)(m0 + r) * N + n0 + c4] = v;
    }
}

// ----------------------------------------------------------------------------
// Generic C = act(A @ B^T + bias). Scalar FFMA (z0 map + final projection).
// ----------------------------------------------------------------------------
template<int ACT>
__global__ void __launch_bounds__(256)
gemm_tn(const float* __restrict__ A, const float* __restrict__ Bm,
        const float* __restrict__ bias, float* __restrict__ C,
        int M, int N, int K)
{
    __shared__ __align__(16) float As[16][64];
    __shared__ __align__(16) float Bs[16][64];
    const int m0 = blockIdx.x * 64;
    const int n0 = blockIdx.y * 64;
    const int tid = threadIdx.x;
    const int tr = tid >> 4;
    const int tc = tid & 15;

    float acc[4][4];
#pragma unroll
    for (int i = 0; i < 4; i++)
#pragma unroll
        for (int j = 0; j < 4; j++) acc[i][j] = 0.f;

    const int ml = tid >> 2;
    const int kq = (tid & 3) * 4;

    for (int k0 = 0; k0 < K; k0 += 16) {
        {
            float4 v = *(const float4*)(A + (size_t)(m0 + ml) * K + k0 + kq);
            As[kq+0][ml] = v.x; As[kq+1][ml] = v.y; As[kq+2][ml] = v.z; As[kq+3][ml] = v.w;
            float4 w = make_float4(0.f, 0.f, 0.f, 0.f);
            if (n0 + ml < N)
                w = *(const float4*)(Bm + (size_t)(n0 + ml) * K + k0 + kq);
            Bs[kq+0][ml] = w.x; Bs[kq+1][ml] = w.y; Bs[kq+2][ml] = w.z; Bs[kq+3][ml] = w.w;
        }
        __syncthreads();
#pragma unroll
        for (int kk = 0; kk < 16; kk++) {
            float4 a4 = *(const float4*)&As[kk][tr*4];
            float4 b4 = *(const float4*)&Bs[kk][tc*4];
            float av[4] = {a4.x, a4.y, a4.z, a4.w};
            float bv[4] = {b4.x, b4.y, b4.z, b4.w};
#pragma unroll
            for (int i = 0; i < 4; i++)
#pragma unroll
                for (int j = 0; j < 4; j++) acc[i][j] += av[i] * bv[j];
        }
        __syncthreads();
    }

#pragma unroll
    for (int j = 0; j < 4; j++) {
        int n = n0 + tc*4 + j;
        if (n >= N) continue;
        float bb = bias ? bias[n] : 0.f;
#pragma unroll
        for (int i = 0; i < 4; i++) {
            float v = acc[i][j] + bb;
            if (ACT == 1) v = tanhf(v);
            else if (ACT == 2) v = fmaxf(v, 0.f);
            C[(size_t)(m0 + tr*4 + i) * N + n] = v;
        }
    }
}

// ----------------------------------------------------------------------------
// Persistent LSTM layer — round-11 version (465us/layer), unchanged.
// ----------------------------------------------------------------------------
__global__ void __launch_bounds__(512)
lstm_persist(const float* __restrict__ xw,
             const float* __restrict__ Whh,
             const float* __restrict__ bih, const float* __restrict__ bhh,
             float* __restrict__ h_buf, int h_sb, int mode, int nsteps, int cbase)
{
    extern __shared__ __align__(16) float Wsm[];
    __shared__ __align__(16) float As[ENC_H][33];
    __shared__ float Gs[32][132];
    __shared__ float bsum[128];

    const int grp = blockIdx.x & 31;
    const int b0 = grp * 32;
    const int h0 = (blockIdx.x >> 5) * 32;
    const int tid = threadIdx.x;
    const int tr = tid >> 5;
    const int tc = tid & 31;

#pragma unroll
    for (int q = 0; q < 8; q++) {
        int e = tid + q * 512;
        int c = e & 127, kq = (e >> 7) * 4;
        int jg = (c >> 5) * ENC_H + h0 + (c & 31);
        float4 v = *(const float4*)(Whh + (size_t)jg * ENC_H + kq);
        Wsm[(kq+0)*128 + c] = v.x; Wsm[(kq+1)*128 + c] = v.y;
        Wsm[(kq+2)*128 + c] = v.z; Wsm[(kq+3)*128 + c] = v.w;
    }
    if (tid < 128) {
        int jg = (tid >> 5) * ENC_H + h0 + (tid & 31);
        bsum[tid] = bih[jg] + bhh[jg];
    }
    float creg[2] = {0.f, 0.f};
    __syncthreads();

    for (int t = 0; t < nsteps; t++) {
        float xr[2][4];
#pragma unroll
        for (int j = 0; j < 4; j++) {
            int c = tc*4 + j;
            int jg = (c >> 5) * ENC_H + h0 + (c & 31);
#pragma unroll
            for (int p = 0; p < 2; p++)
                xr[p][j] = xw[(size_t)(b0 + 2*tr + p) * (T_HIST*G4)
                              + (size_t)t * G4 + jg];
        }

        float acc[2][4];
#pragma unroll
        for (int p = 0; p < 2; p++)
#pragma unroll
            for (int j = 0; j < 4; j++) acc[p][j] = 0.f;

        if (t > 0) {
            if (tid == 0) {
                while (__ldcg(&g_grpCnt[cbase + grp]) < 4u * (unsigned)t)
                    __nanosleep(20);
            }
            __syncthreads();
            const float* hp = h_buf + (mode ? (size_t)((t-1) & 1) * BB * ENC_H
                                            : (size_t)(t-1) * ENC_H);
#pragma unroll
            for (int q = 0; q < 2; q++) {
                int e = tid + q * 512;
                int m = e & 31, kq = (e >> 5) * 4;
                float4 v = __ldcg((const float4*)(hp + (size_t)(b0 + m) * h_sb + kq));
                As[kq+0][m] = v.x; As[kq+1][m] = v.y; As[kq+2][m] = v.z; As[kq+3][m] = v.w;
            }
            __syncthreads();
#pragma unroll 8
            for (int kk = 0; kk < ENC_H; kk++) {
                float a0 = As[kk][2*tr];
                float a1 = As[kk][2*tr + 1];
                float4 w = *(const float4*)&Wsm[kk*128 + tc*4];
                acc[0][0] += a0 * w.x; acc[0][1] += a0 * w.y;
                acc[0][2] += a0 * w.z; acc[0][3] += a0 * w.w;
                acc[1][0] += a1 * w.x; acc[1][1] += a1 * w.y;
                acc[1][2] += a1 * w.z; acc[1][3] += a1 * w.w;
            }
        }

#pragma unroll
        for (int j = 0; j < 4; j++) {
            int c = tc*4 + j;
            float bb = bsum[c];
#pragma unroll
            for (int p = 0; p < 2; p++) {
                int r = 2*tr + p;
                Gs[r][c] = acc[p][j] + xr[p][j] + bb;
            }
        }
        __syncthreads();

        float* ho = h_buf + (mode ? (size_t)(t & 1) * BB * ENC_H : (size_t)t * ENC_H);
#pragma unroll
        for (int q = 0; q < 2; q++) {
            int e = tid + q * 512;
            int r = e >> 5, hh = e & 31;
            float gi = Gs[r][hh];
            float gf = Gs[r][32 + hh];
            float gg = Gs[r][64 + hh];
            float go = Gs[r][96 + hh];
            float si = 1.f / (1.f + expf(-gi));
            float sf = 1.f / (1.f + expf(-gf));
            float so = 1.f / (1.f + expf(-go));
            float tg = tanhf(gg);
            float cn = sf * creg[q] + si * tg;
            creg[q] = cn;
            float hn = so * tanhf(cn);
            ho[(size_t)(b0 + r) * h_sb + h0 + hh] = hn;
        }
        __syncthreads();
        if (tid == 0) {
            __threadfence();
            atomicAdd(&g_grpCnt[cbase + grp], 1u);
        }
    }
}

// ----------------------------------------------------------------------------
// Fused CDE kernel: contract(stage sidx) + prep(next stage).
// grid = 256 CTAs (4 batch rows each), 128 threads. High CTA count keeps the
// 8.6MB g_f read latency-spread (round-6 fusion failed at 32 CTAs).
// ----------------------------------------------------------------------------
__global__ void __launch_bounds__(128)
cde_cp(const float* __restrict__ coeffs,
       const float* __restrict__ gamma, const float* __restrict__ beta,
       const float* __restrict__ W1, const float* __restrict__ b1,
       int do_contract, int sidx, int idx, float u, int is_last,
       float c1, float c3, float c4, float c5, float c6,
       int do_prep, float a0, float a1, float a2, float a3, float a4, int nk)
{
    __shared__ float W1s[64 * 128];              // 32KB, [k][j]
    __shared__ float zs[4][65];
    __shared__ float dXs[4][CHN];
    __shared__ __align__(16) float znT[64][4];
    const int r0 = blockIdx.x * 4;
    const int tid = threadIdx.x;

    if (do_prep) {
        // W1 transposed load (independent of contract — overlaps f reads)
#pragma unroll
        for (int q = 0; q < 64; q++) {
            int e = tid + q * 128;
            int j = e >> 6, k = e & 63;
            W1s[k * 128 + j] = W1[e];
        }
    }

    if (do_contract) {
        for (int e = tid; e < 4 * CHN; e += 128) {
            int r = e / CHN, ch = e - r * CHN;
            size_t base = ((size_t)(r0 + r) * 4 + idx) * (4 * CHN);
            float A1 = coeffs[base + CHN + ch];
            float A2 = coeffs[base + 2 * CHN + ch];
            float A3 = coeffs[base + 3 * CHN + ch];
            dXs[r][ch] = A1 + 2.f * A2 * u + 3.f * A3 * u * u;
        }
        __syncthreads();
        const float av[5] = {a0, a1, a2, a3, a4};
#pragma unroll
        for (int q = 0; q < 2; q++) {
            int e = tid + q * 128;
            int r = e >> 6, h = e & 63;
            const float* fr = g_f + (size_t)(r0 + r) * W2_ROWS + h * CHN;
            float acc = 0.f;
#pragma unroll
            for (int ch = 0; ch < CHN; ch++) acc += fr[ch] * dXs[r][ch];
            size_t gi = (size_t)(r0 + r) * CDE_H + h;
            if (is_last) {
                float z = g_z[gi] + c1 * g_k[0][gi] + c3 * g_k[2][gi]
                        + c4 * g_k[3][gi] + c5 * g_k[4][gi] + c6 * acc;
                g_z[gi] = z;
                zs[r][h] = z;
            } else {
                g_k[sidx][gi] = acc;
                float v = g_z[gi];
                for (int j = 0; j < nk; j++)
                    v += av[j] * ((j == sidx) ? acc : g_k[j][gi]);
                zs[r][h] = v;
            }
        }
    } else {
#pragma unroll
        for (int q = 0; q < 2; q++) {
            int e = tid + q * 128;
            int r = e >> 6, h = e & 63;
            zs[r][h] = g_z[(size_t)(r0 + r) * CDE_H + h];
        }
    }
    if (!do_prep) return;
    __syncthreads();

    // LayerNorm: warp w handles row w (32 lanes x 2 cols)
    {
        int w = tid >> 5, lane = tid & 31;
        float x0 = zs[w][lane], x1 = zs[w][lane + 32];
        float s = x0 + x1;
#pragma unroll
        for (int d = 1; d < 32; d <<= 1) s += __shfl_xor_sync(0xffffffffu, s, d);
        float m = s * (1.f / 64.f);
        float d0 = x0 - m, d1 = x1 - m;
        float q2 = d0 * d0 + d1 * d1;
#pragma unroll
        for (int d = 1; d < 32; d <<= 1) q2 += __shfl_xor_sync(0xffffffffu, q2, d);
        float rs = rsqrtf(q2 * (1.f / 64.f) + 1e-5f);
        znT[lane][w]      = d0 * rs * gamma[lane] + beta[lane];
        znT[lane + 32][w] = d1 * rs * gamma[lane + 32] + beta[lane + 32];
    }
    __syncthreads();

    // GEMM: thread tid owns MLP col tid for 4 rows
    float acc4[4] = {0.f, 0.f, 0.f, 0.f};
#pragma unroll 8
    for (int k = 0; k < 64; k++) {
        float4 z4 = *(const float4*)&znT[k][0];
        float wv = W1s[k * 128 + tid];
        acc4[0] += z4.x * wv; acc4[1] += z4.y * wv;
        acc4[2] += z4.z * wv; acc4[3] += z4.w * wv;
    }
    float bb = b1[tid];
    int ks = tid >> 3, k8 = tid & 7;
#pragma unroll
    for (int i = 0; i < 4; i++) {
        int r = r0 + i;
        float v = fmaxf(acc4[i] + bb, 0.f);
        unsigned hb = f2tf32(v);
        unsigned lb = f2tf32(v - __uint_as_float(hb));
        int mt = r >> 4, r16 = r & 15;
        int lane = (r16 & 7) * 4 + (k8 & 3);
        int slot = ((r16 >> 3) & 1) | ((k8 >> 2) << 1);
        int idxF = ((ks * 64 + mt) * 2) * 128 + lane * 4 + slot;
        g_aF[idxF] = hb;
        g_aF[idxF + 128] = lb;
    }
}

// ----------------------------------------------------------------------------
// Host orchestration
// ----------------------------------------------------------------------------
extern "C" void kernel_launch(void* const* d_in, const int* in_sizes, int n_in,
                              void* d_out, int out_size)
{
    const float* hist   = (const float*)d_in[0];
    const float* coeffs = (const float*)d_in[1];
    const float* W_ih0 = (const float*)d_in[3];
    const float* W_hh0 = (const float*)d_in[4];
    const float* b_ih0 = (const float*)d_in[5];
    const float* b_hh0 = (const float*)d_in[6];
    const float* W_ih1 = (const float*)d_in[7];
    const float* W_hh1 = (const float*)d_in[8];
    const float* b_ih1 = (const float*)d_in[9];
    const float* b_hh1 = (const float*)d_in[10];
    const float* W_map = (const float*)d_in[11];
    const float* b_map = (const float*)d_in[12];
    const float* gamma = (const float*)d_in[13];
    const float* beta  = (const float*)d_in[14];
    const float* W1    = (const float*)d_in[15];
    const float* b1    = (const float*)d_in[16];
    const float* W2    = (const float*)d_in[17];
    const float* b2    = (const float*)d_in[18];
    const float* W_pred = (const float*)d_in[19];
    const float* b_pred = (const float*)d_in[20];
    float* out = (float*)d_out;

    float *p_xW, *p_seq0, *p_h1, *p_z, *p_f;
    cudaGetSymbolAddress((void**)&p_xW,   g_xW);
    cudaGetSymbolAddress((void**)&p_seq0, g_seq0);
    cudaGetSymbolAddress((void**)&p_h1,   g_h1);
    cudaGetSymbolAddress((void**)&p_z,    g_z);
    cudaGetSymbolAddress((void**)&p_f,    g_f);

    const int WSM_BYTES = 128 * 128 * 4;
    const int TC_SMEM = 12288 * 4;
    cudaFuncSetAttribute(lstm_persist, cudaFuncAttributeMaxDynamicSharedMemorySize, WSM_BYTES);
    cudaFuncSetAttribute(gemm_w2_tc, cudaFuncAttributeMaxDynamicSharedMemorySize, TC_SMEM);
    cudaFuncSetAttribute(gemm_tf32, cudaFuncAttributeMaxDynamicSharedMemorySize, TC_SMEM);

    zero_cnt<<<1, 64>>>();
    w2_frag<<<(W2_ROWS*128 + 255)/256, 256>>>(W2);

    // ---------------- LSTM layer 0 ----------------
    gemm_tf32<<<dim3(BB*T_HIST/128, G4/64), 256, TC_SMEM>>>(hist, W_ih0, nullptr, p_xW,
                                                            BB*T_HIST, G4, ENC_IN);
    lstm_persist<<<128, 512, WSM_BYTES>>>(p_xW, W_hh0, b_ih0, b_hh0,
                                          p_seq0, T_HIST*ENC_H, 0, T_HIST, 0);

    // ---------------- LSTM layer 1 ----------------
    gemm_tf32<<<dim3(BB*T_HIST/128, G4/64), 256, TC_SMEM>>>(p_seq0, W_ih1, nullptr, p_xW,
                                                            BB*T_HIST, G4, ENC_H);
    lstm_persist<<<128, 512, WSM_BYTES>>>(p_xW, W_hh1, b_ih1, b_hh1,
                                          p_h1, ENC_H, 1, T_HIST, 32);
    const float* context = p_h1 + (size_t)((T_HIST - 1) & 1) * BB * ENC_H;

    // ---------------- map to z0 ----------------
    gemm_tn<1><<<dim3(BB/64, 1), 256>>>(context, W_map, b_map, p_z, BB, CDE_H, ENC_H);

    // ---------------- Neural CDE, RK45 (Dormand-Prince) ----------------
    const double dt = 1.0 / N_STEPS;
    const double ACF[6][5] = {
        {0, 0, 0, 0, 0},
        {1.0/5, 0, 0, 0, 0},
        {3.0/40, 9.0/40, 0, 0, 0},
        {44.0/45, -56.0/15, 32.0/9, 0, 0},
        {19372.0/6561, -25360.0/2187, 64448.0/6561, -212.0/729, 0},
        {9017.0/3168, -355.0/33, 46732.0/5247, 49.0/176, -5103.0/18656}
    };
    const double COFF[6] = {0.0, 1.0/5, 3.0/10, 4.0/5, 8.0/9, 1.0};
    const double BU[5] = {35.0/384, 500.0/1113, 125.0/192, -2187.0/6784, 11.0/84};

    // initial prep for (i=0, s=0): no contract, nk=0
    cde_cp<<<256, 128>>>(coeffs, gamma, beta, W1, b1,
        0, 0, 0, 0.f, 0, 0.f, 0.f, 0.f, 0.f, 0.f,
        1, 0.f, 0.f, 0.f, 0.f, 0.f, 0);

    for (int it = 0; it < 96; it++) {
        int i = it / 6, s = it % 6;

        gemm_w2_tc<<<dim3(BB/128, W2_ROWS/64), 256, TC_SMEM>>>(b2, p_f);

        float ts = (float)((i + COFF[s]) * dt);
        int idx = (int)floorf(ts / 0.25f);
        if (idx < 0) idx = 0;
        if (idx > 3) idx = 3;
        float u = ts - (float)idx * 0.25f;

        int last = (s == 5);
        int do_prep = (it < 95);
        int nk = last ? 0 : (s + 1);
        const double* ar = last ? ACF[0] : ACF[s + 1];

        cde_cp<<<256, 128>>>(coeffs, gamma, beta, W1, b1,
            1, s, idx, u, last,
            (float)(dt*BU[0]), (float)(dt*BU[1]), (float)(dt*BU[2]),
            (float)(dt*BU[3]), (float)(dt*BU[4]),
            do_prep,
            (float)(dt*ar[0]), (float)(dt*ar[1]), (float)(dt*ar[2]),
            (float)(dt*ar[3]), (float)(dt*ar[4]), nk);
    }

    // ---------------- final projection ----------------
    gemm_tn<0><<<dim3(BB/64, (NZ + 63)/64), 256>>>(p_z, W_pred, b_pred, out,
                                                   BB, NZ, CDE_H);
}